// round 12
// baseline (speedup 1.0000x reference)
#include <cuda_runtime.h>
#include <cuda_bf16.h>
#include <math.h>
#include <stdint.h>

#define NN 100000
#define EE 600000
#define GG 512
#define HH 128
#define KP0 80          // layer0 K padded (74 -> 80)
#define KR0 74
#define SCAN_B 512
#define NSB ((NN + SCAN_B - 1) / SCAN_B)   // 196
#define CS 132          // smem C row stride (floats)
#define BUFSZ 65536     // per-pipeline-buffer smem stride
#define SAGE_GRID 148

// ---- scratch (device globals; no allocation allowed) ----
// packed layout: per node, per 4-channel group q: uint4{hi01, hi23, lo01, lo23}
__device__ uint4 d_h0p[NN * (KP0 / 4)];
__device__ uint4 d_h1p[NN * (HH / 4)];
__device__ uint4 d_aggp[NN * (HH / 4)];
__device__ __nv_bfloat16 d_w0hi[160 * HH];
__device__ __nv_bfloat16 d_w0lo[160 * HH];
__device__ __nv_bfloat16 d_w1hi[256 * HH];
__device__ __nv_bfloat16 d_w1lo[256 * HH];
__device__ float d_invdeg[NN];
__device__ int   d_degi[NN];
__device__ int   d_cursor[NN];
__device__ int   d_rowstart[NN + 1];
__device__ int   d_eid[EE];
__device__ int   d_bsum[NSB];
__device__ float d_psum[GG * HH];
__device__ float d_pmax[GG * HH];
__device__ float d_cnt[GG];

// ============================ helpers ======================================
__device__ __forceinline__ uint32_t smem_u32(const void* p) {
    uint32_t a;
    asm("{ .reg .u64 t; cvta.to.shared.u64 t, %1; cvt.u32.u64 %0, t; }"
        : "=r"(a) : "l"(p));
    return a;
}
__device__ __forceinline__ uint32_t sw128(uint32_t off) { return off ^ ((off >> 3) & 0x70); }
__device__ __forceinline__ uint32_t bpack(__nv_bfloat16 a, __nv_bfloat16 b) {
    return ((uint32_t)__bfloat16_as_ushort(b) << 16) | (uint32_t)__bfloat16_as_ushort(a);
}
__device__ __forceinline__ void ldsm4(uint32_t& r0, uint32_t& r1,
                                      uint32_t& r2, uint32_t& r3, uint32_t addr) {
    asm volatile("ldmatrix.sync.aligned.m8n8.x4.shared.b16 {%0,%1,%2,%3}, [%4];"
                 : "=r"(r0), "=r"(r1), "=r"(r2), "=r"(r3) : "r"(addr));
}
__device__ __forceinline__ void mma16816(float* d, const uint32_t* a,
                                         uint32_t b0, uint32_t b1) {
    asm volatile("mma.sync.aligned.m16n8k16.row.col.f32.bf16.bf16.f32 "
                 "{%0,%1,%2,%3}, {%4,%5,%6,%7}, {%8,%9}, {%0,%1,%2,%3};"
                 : "+f"(d[0]), "+f"(d[1]), "+f"(d[2]), "+f"(d[3])
                 : "r"(a[0]), "r"(a[1]), "r"(a[2]), "r"(a[3]), "r"(b0), "r"(b1));
}
__device__ __forceinline__ float2 b2f2(uint32_t u) {
    return __bfloat1622float2(*reinterpret_cast<__nv_bfloat162*>(&u));
}
__device__ __forceinline__ uint4 pack4(float a0, float a1, float a2, float a3) {
    __nv_bfloat16 b0 = __float2bfloat16(a0), b1 = __float2bfloat16(a1);
    __nv_bfloat16 b2 = __float2bfloat16(a2), b3 = __float2bfloat16(a3);
    uint4 r;
    r.x = bpack(b0, b1);
    r.y = bpack(b2, b3);
    r.z = bpack(__float2bfloat16(a0 - __bfloat162float(b0)),
                __float2bfloat16(a1 - __bfloat162float(b1)));
    r.w = bpack(__float2bfloat16(a2 - __bfloat162float(b2)),
                __float2bfloat16(a3 - __bfloat162float(b3)));
    return r;
}
__device__ __forceinline__ void cp_async16(uint32_t dst, const void* src, bool full) {
    int sz = full ? 16 : 0;
    asm volatile("cp.async.cg.shared.global [%0], [%1], 16, %2;"
                 :: "r"(dst), "l"(src), "r"(sz) : "memory");
}
#define CP_COMMIT() asm volatile("cp.async.commit_group;" ::: "memory")
#define CP_WAIT0()  asm volatile("cp.async.wait_group 0;" ::: "memory")

// ===========================================================================
// init (deg/cursor/pool buffers) + packed h0 build + BOTH layers' weight prep
__global__ void k_initprep(const float* __restrict__ x,
                           const float* __restrict__ xd,
                           const int* __restrict__ st,
                           const float* __restrict__ emb,
                           const float* __restrict__ Wl0, const float* __restrict__ Wr0,
                           const float* __restrict__ Wl1, const float* __restrict__ Wr1) {
    int idx = blockIdx.x * blockDim.x + threadIdx.x;
    if (idx < NN) { d_degi[idx] = 0; d_cursor[idx] = 0; }
    if (idx < GG * HH) { d_psum[idx] = 0.f; d_pmax[idx] = __int_as_float(0xFF800000); }
    if (idx < GG) d_cnt[idx] = 0.f;

    constexpr int KT0 = 2 * KP0;          // 160
    constexpr int KT1 = 2 * HH;           // 256
    constexpr int N0 = HH * KT0;          // 20480
    if (idx < N0) {
        int o = idx / KT0;
        int k = idx - o * KT0;
        float w = 0.f;
        const float* W = (k < KP0) ? Wl0 : Wr0;
        int r = (k < KP0) ? k : k - KP0;
        if (r < KR0) w = W[(size_t)r * HH + o];
        __nv_bfloat16 hi = __float2bfloat16(w);
        d_w0hi[idx] = hi;
        d_w0lo[idx] = __float2bfloat16(w - __bfloat162float(hi));
    }
    int idx1 = idx - N0;
    if (idx1 >= 0 && idx1 < HH * KT1) {
        int o = idx1 / KT1;
        int k = idx1 - o * KT1;
        const float* W = (k < HH) ? Wl1 : Wr1;
        int r = (k < HH) ? k : k - HH;
        float w = W[(size_t)r * HH + o];
        __nv_bfloat16 hi = __float2bfloat16(w);
        d_w1hi[idx1] = hi;
        d_w1lo[idx1] = __float2bfloat16(w - __bfloat162float(hi));
    }

    constexpr int C4 = KP0 / 4;
    if (idx >= NN * C4) return;
    int n = idx / C4;
    int q = idx - n * C4;
    float v[4];
#pragma unroll
    for (int t = 0; t < 4; t++) {
        int j = q * 4 + t;
        if (j < 60)      v[t] = x[n * 60 + j];
        else if (j < 62) v[t] = xd[n * 2 + (j - 60)];
        else if (j < 74) v[t] = emb[st[n] * 12 + (j - 62)];
        else             v[t] = 0.f;
    }
    d_h0p[idx] = pack4(v[0], v[1], v[2], v[3]);
}

__global__ void k_deg(const int* __restrict__ dst) {
    int e = blockIdx.x * blockDim.x + threadIdx.x;
    if (e < EE) atomicAdd(&d_degi[dst[e]], 1);
}

__global__ void __launch_bounds__(SCAN_B)
k_scan1() {
    __shared__ int sc[SCAN_B];
    int tid = threadIdx.x;
    int i = blockIdx.x * SCAN_B + tid;
    int v = (i < NN) ? d_degi[i] : 0;
    sc[tid] = v;
    __syncthreads();
#pragma unroll
    for (int off = 1; off < SCAN_B; off <<= 1) {
        int t = (tid >= off) ? sc[tid - off] : 0;
        __syncthreads();
        sc[tid] += t;
        __syncthreads();
    }
    if (i < NN) {
        d_rowstart[i] = sc[tid] - v;
        d_invdeg[i] = 1.f / fmaxf((float)v, 1.f);
    }
    if (tid == SCAN_B - 1) d_bsum[blockIdx.x] = sc[tid];
}

// scan of block sums (done redundantly per block) + rowstart offset + graph count
__global__ void __launch_bounds__(256)
k_scan3c(const int* __restrict__ batch) {
    __shared__ int sc[256];
    __shared__ int ex[256];
    int tid = threadIdx.x;
    int v = (tid < NSB) ? d_bsum[tid] : 0;
    sc[tid] = v;
    __syncthreads();
#pragma unroll
    for (int off = 1; off < 256; off <<= 1) {
        int t = (tid >= off) ? sc[tid - off] : 0;
        __syncthreads();
        sc[tid] += t;
        __syncthreads();
    }
    ex[tid] = sc[tid] - v;
    __syncthreads();

    int i = blockIdx.x * 256 + tid;
    if (i < NN) {
        d_rowstart[i] += ex[i / SCAN_B];
        atomicAdd(&d_cnt[batch[i]], 1.f);
    }
    if (blockIdx.x == 0 && tid == 0) d_rowstart[NN] = EE;
}

__global__ void k_fill(const int* __restrict__ src, const int* __restrict__ dst) {
    int e = blockIdx.x * blockDim.x + threadIdx.x;
    if (e >= EE) return;
    int dn = dst[e];
    int pos = d_rowstart[dn] + atomicAdd(&d_cursor[dn], 1);
    d_eid[pos] = src[e];
}

// gather aggregation, layer1 (C4 = 32): one warp per node, unroll x2.
__global__ void __launch_bounds__(128)
k_gatherp(const uint4* __restrict__ hp) {
    int n = blockIdx.x * 4 + (threadIdx.x >> 5);
    int lane = threadIdx.x & 31;
    if (n >= NN) return;
    constexpr int C4 = HH / 4;
    int s = d_rowstart[n];
    int e = d_rowstart[n + 1];
    float a0 = 0.f, a1 = 0.f, a2 = 0.f, a3 = 0.f;
    int j = s;
    for (; j + 1 < e; j += 2) {
        int id0 = d_eid[j];
        int id1 = d_eid[j + 1];
        uint4 v0 = hp[(size_t)id0 * C4 + lane];
        uint4 v1 = hp[(size_t)id1 * C4 + lane];
        float2 h01 = b2f2(v0.x), h23 = b2f2(v0.y);
        float2 l01 = b2f2(v0.z), l23 = b2f2(v0.w);
        a0 += h01.x + l01.x; a1 += h01.y + l01.y;
        a2 += h23.x + l23.x; a3 += h23.y + l23.y;
        h01 = b2f2(v1.x); h23 = b2f2(v1.y);
        l01 = b2f2(v1.z); l23 = b2f2(v1.w);
        a0 += h01.x + l01.x; a1 += h01.y + l01.y;
        a2 += h23.x + l23.x; a3 += h23.y + l23.y;
    }
    if (j < e) {
        uint4 v0 = hp[(size_t)d_eid[j] * C4 + lane];
        float2 h01 = b2f2(v0.x), h23 = b2f2(v0.y);
        float2 l01 = b2f2(v0.z), l23 = b2f2(v0.w);
        a0 += h01.x + l01.x; a1 += h01.y + l01.y;
        a2 += h23.x + l23.x; a3 += h23.y + l23.y;
    }
    float inv = d_invdeg[n];
    d_aggp[(size_t)n * C4 + lane] = pack4(a0 * inv, a1 * inv, a2 * inv, a3 * inv);
}

// gather aggregation, layer0 (C4 = 20): 160 threads, 20 lanes/node, 8 nodes/block.
__global__ void __launch_bounds__(160)
k_gatherp0(const uint4* __restrict__ hp) {
    constexpr int C4 = KP0 / 4;           // 20
    int tid = threadIdx.x;
    int n = blockIdx.x * 8 + tid / C4;
    int lane = tid % C4;
    if (n >= NN) return;
    int s = d_rowstart[n];
    int e = d_rowstart[n + 1];
    float a0 = 0.f, a1 = 0.f, a2 = 0.f, a3 = 0.f;
    int j = s;
    for (; j + 1 < e; j += 2) {
        int id0 = d_eid[j];
        int id1 = d_eid[j + 1];
        uint4 v0 = hp[(size_t)id0 * C4 + lane];
        uint4 v1 = hp[(size_t)id1 * C4 + lane];
        float2 h01 = b2f2(v0.x), h23 = b2f2(v0.y);
        float2 l01 = b2f2(v0.z), l23 = b2f2(v0.w);
        a0 += h01.x + l01.x; a1 += h01.y + l01.y;
        a2 += h23.x + l23.x; a3 += h23.y + l23.y;
        h01 = b2f2(v1.x); h23 = b2f2(v1.y);
        l01 = b2f2(v1.z); l23 = b2f2(v1.w);
        a0 += h01.x + l01.x; a1 += h01.y + l01.y;
        a2 += h23.x + l23.x; a3 += h23.y + l23.y;
    }
    if (j < e) {
        uint4 v0 = hp[(size_t)d_eid[j] * C4 + lane];
        float2 h01 = b2f2(v0.x), h23 = b2f2(v0.y);
        float2 l01 = b2f2(v0.z), l23 = b2f2(v0.w);
        a0 += h01.x + l01.x; a1 += h01.y + l01.y;
        a2 += h23.x + l23.x; a3 += h23.y + l23.y;
    }
    float inv = d_invdeg[n];
    d_aggp[(size_t)n * C4 + lane] = pack4(a0 * inv, a1 * inv, a2 * inv, a3 * inv);
}

// ===========================================================================
// Persistent HMMA fused SAGE layer: grid=148, each block streams (tile,chunk)
// pairs with depth-1 software pipelining ACROSS tile boundaries. sC has its
// own smem region so epilogues overlap in-flight staging for the next tile.
// ===========================================================================
template <int KP, bool POOL>
__global__ void __launch_bounds__(256, 1)
k_sage_hmma(const float* __restrict__ bl, const float* __restrict__ g,
            const float* __restrict__ bn,
            const uint4* __restrict__ hp,
            const __nv_bfloat16* __restrict__ whi,
            const __nv_bfloat16* __restrict__ wlo,
            uint4* __restrict__ outp,
            const int* __restrict__ batch) {
    extern __shared__ __align__(128) char smem[];
    constexpr int KT = 2 * KP;
    constexpr int NCH = (KT + 63) / 64;
    constexpr int C4 = KP / 4;
    const uint32_t sb = smem_u32(smem);
    const int tid = threadIdx.x;
    const int wid = tid >> 5;
    const int lid = tid & 31;
    const int wm = wid & 1;
    const int wn = wid >> 1;
    const int G = gridDim.x;

    const int NT = (NN + 127) / 128;
    const int myTiles = ((int)blockIdx.x < NT) ? ((NT - 1 - (int)blockIdx.x) / G + 1) : 0;
    const int total = myTiles * NCH;
    if (total == 0) return;

    float* sC   = (float*)(smem + 2 * BUFSZ);          // 131072, 67584 bytes
    float* s_bl = (float*)(smem + 2 * BUFSZ + 67584);
    float* s_g  = s_bl + 128;
    float* s_bn = s_bl + 256;
    float* s_mu = s_bl + 384;
    float* s_rs = s_bl + 512;
    int*  sbat  = (int*)(s_bl + 640);

    if (tid < 128) { s_bl[tid] = bl[tid]; s_g[tid] = g[tid]; s_bn[tid] = bn[tid]; }

    float acc[4][4][4];
#pragma unroll
    for (int mt = 0; mt < 4; mt++)
#pragma unroll
        for (int nt = 0; nt < 4; nt++)
#pragma unroll
            for (int j = 0; j < 4; j++) acc[mt][nt][j] = 0.f;

    uint4 rh[4], rl[4];

    auto stageA_ldg = [&](int n0s, int c) {
#pragma unroll
        for (int it = 0; it < 4; it++) {
            int idx = tid + it * 256;
            int m = idx >> 3, j = idx & 7;
            int kg = c * 64 + j * 8;
            int n = n0s + m;
            uint4 p0 = make_uint4(0, 0, 0, 0), p1 = make_uint4(0, 0, 0, 0);
            if (n < NN && kg < KT) {
                const uint4* P;
                int kl;
                if (kg < KP) { P = d_aggp; kl = kg; } else { P = hp; kl = kg - KP; }
                size_t base = (size_t)n * C4 + (kl >> 2);
                p0 = P[base]; p1 = P[base + 1];
            }
            rh[it] = make_uint4(p0.x, p0.y, p1.x, p1.y);
            rl[it] = make_uint4(p0.z, p0.w, p1.z, p1.w);
        }
    };
    auto stageA_sts = [&](int pb) {
#pragma unroll
        for (int it = 0; it < 4; it++) {
            int idx = tid + it * 256;
            int m = idx >> 3, j = idx & 7;
            uint32_t sw = sw128((uint32_t)m * 128 + j * 16);
            *(uint4*)(smem + pb * BUFSZ + sw)         = rh[it];
            *(uint4*)(smem + pb * BUFSZ + 16384 + sw) = rl[it];
        }
    };
    auto stageB_cp = [&](int c, int pb) {
#pragma unroll
        for (int it = 0; it < 4; it++) {
            int idx = tid + it * 256;
            int o = idx >> 3, j = idx & 7;
            int kg = c * 64 + j * 8;
            bool ok = (kg < KT);
            size_t off = ok ? ((size_t)o * KT + kg) : 0;
            uint32_t sw = sw128((uint32_t)o * 128 + j * 16);
            cp_async16(sb + pb * BUFSZ + 32768 + sw, &whi[off], ok);
            cp_async16(sb + pb * BUFSZ + 49152 + sw, &wlo[off], ok);
        }
    };

    // ---- prologue: stage stream element 0 ----
    stageA_ldg((int)blockIdx.x * 128, 0);
    stageB_cp(0, 0);
    CP_COMMIT();
    stageA_sts(0);
    CP_WAIT0();
    __syncthreads();

    for (int s = 0; s < total; s++) {
        const int pb = s & 1;
        const int c = s % NCH;
        const int tile = (int)blockIdx.x + (s / NCH) * G;
        const int n0 = tile * 128;

        if (s + 1 < total) {
            int s1 = s + 1;
            int c1 = s1 % NCH;
            int t1 = (int)blockIdx.x + (s1 / NCH) * G;
            stageA_ldg(t1 * 128, c1);
            stageB_cp(c1, pb ^ 1);
            CP_COMMIT();
        }

        // ---- compute chunk c from buffer pb ----
        const uint32_t AHI = sb + pb * BUFSZ, ALO = AHI + 16384;
        const uint32_t BHI = AHI + 32768,     BLO = AHI + 49152;
        const int steps = min(4, (KT - c * 64) / 16);
#pragma unroll
        for (int ks = 0; ks < 4; ks++) {
            if (ks >= steps) break;
            const int kof = ks * 16 + (((lid >> 4) & 1) << 3);
            const int rsub = (lid & 7) + ((lid >> 3) & 1) * 8;

            uint32_t ah[4][4], al[4][4];
#pragma unroll
            for (int mt = 0; mt < 4; mt++) {
                int row = wm * 64 + mt * 16 + rsub;
                uint32_t o = sw128((uint32_t)row * 128 + kof * 2);
                ldsm4(ah[mt][0], ah[mt][1], ah[mt][2], ah[mt][3], AHI + o);
                ldsm4(al[mt][0], al[mt][1], al[mt][2], al[mt][3], ALO + o);
            }
            uint32_t bh[2][4], blo[2][4];
#pragma unroll
            for (int ng = 0; ng < 2; ng++) {
                int rown = wn * 32 + ng * 16 + rsub;
                uint32_t o = sw128((uint32_t)rown * 128 + kof * 2);
                ldsm4(bh[ng][0], bh[ng][1], bh[ng][2], bh[ng][3], BHI + o);
                ldsm4(blo[ng][0], blo[ng][1], blo[ng][2], blo[ng][3], BLO + o);
            }
#pragma unroll
            for (int mt = 0; mt < 4; mt++)
#pragma unroll
                for (int nt = 0; nt < 4; nt++) {
                    int ng = nt >> 1, sel = nt & 1;
                    mma16816(acc[mt][nt], ah[mt], bh[ng][sel], bh[ng][sel + 2]);
                    mma16816(acc[mt][nt], ah[mt], blo[ng][sel], blo[ng][sel + 2]);
                    mma16816(acc[mt][nt], al[mt], bh[ng][sel], bh[ng][sel + 2]);
                }
        }

        if (s + 1 < total) stageA_sts(pb ^ 1);   // free A regs before epilogue

        if (c == NCH - 1) {
            // ================= tile epilogue (overlaps in-flight cp.async) ==
            if (POOL && tid < 128) sbat[tid] = (n0 + tid < NN) ? batch[n0 + tid] : 0;
            __syncthreads();   // prior tile pool reads done; sbat visible
#pragma unroll
            for (int mt = 0; mt < 4; mt++)
#pragma unroll
                for (int nt = 0; nt < 4; nt++) {
                    int r0 = wm * 64 + mt * 16 + (lid >> 2);
                    int c0 = wn * 32 + nt * 8 + 2 * (lid & 3);
                    sC[r0 * CS + c0]           = acc[mt][nt][0];
                    sC[r0 * CS + c0 + 1]       = acc[mt][nt][1];
                    sC[(r0 + 8) * CS + c0]     = acc[mt][nt][2];
                    sC[(r0 + 8) * CS + c0 + 1] = acc[mt][nt][3];
                    acc[mt][nt][0] = 0.f; acc[mt][nt][1] = 0.f;
                    acc[mt][nt][2] = 0.f; acc[mt][nt][3] = 0.f;
                }
            __syncthreads();

            if (tid < 128) {
                float sum = 0.f, sq = 0.f;
                for (int cc = 0; cc < 128; cc++) {
                    float v = sC[tid * CS + cc] + s_bl[cc];
                    sum += v; sq += v * v;
                }
                float mu = sum * (1.f / HH);
                float var = fmaxf(sq * (1.f / HH) - mu * mu, 0.f);
                s_mu[tid] = mu;
                s_rs[tid] = rsqrtf(var + 1e-5f);
            }
            __syncthreads();

            if (POOL) {
                if (tid < 128) {
                    int vrows = min(128, NN - n0);
                    float gc = s_g[tid], bc = s_bn[tid], blc = s_bl[tid];
                    float ps = 0.f, mx = -__int_as_float(0x7F800000);
                    int cur = sbat[0];
                    for (int m = 0; m < vrows; m++) {
                        int b = sbat[m];
                        if (b != cur) {
                            atomicAdd(&d_psum[cur * HH + tid], ps);
                            atomicMax((int*)&d_pmax[cur * HH + tid], __float_as_int(mx));
                            ps = 0.f; mx = -__int_as_float(0x7F800000); cur = b;
                        }
                        float v = sC[m * CS + tid] + blc;
                        float y = fmaxf((v - s_mu[m]) * s_rs[m] * gc + bc, 0.f);
                        ps += y; mx = fmaxf(mx, y);
                    }
                    atomicAdd(&d_psum[cur * HH + tid], ps);
                    atomicMax((int*)&d_pmax[cur * HH + tid], __float_as_int(mx));
                }
            } else {
                for (int idx = tid; idx < 128 * 32; idx += 256) {
                    int m = idx >> 5, q = idx & 31;
                    int n = n0 + m;
                    if (n >= NN) continue;
                    float mu = s_mu[m], rs = s_rs[m];
                    float4 v = *(const float4*)&sC[m * CS + q * 4];
                    float y0 = fmaxf((v.x + s_bl[q*4+0] - mu) * rs * s_g[q*4+0] + s_bn[q*4+0], 0.f);
                    float y1 = fmaxf((v.y + s_bl[q*4+1] - mu) * rs * s_g[q*4+1] + s_bn[q*4+1], 0.f);
                    float y2 = fmaxf((v.z + s_bl[q*4+2] - mu) * rs * s_g[q*4+2] + s_bn[q*4+2], 0.f);
                    float y3 = fmaxf((v.w + s_bl[q*4+3] - mu) * rs * s_g[q*4+3] + s_bn[q*4+3], 0.f);
                    outp[(size_t)n * 32 + q] = pack4(y0, y1, y2, y3);
                }
            }
        }

        if (s + 1 < total) CP_WAIT0();
        __syncthreads();
    }
}

__global__ void __launch_bounds__(64)
k_mlp(const float* __restrict__ Wf0, const float* __restrict__ bf0,
      const float* __restrict__ Wf1, const float* __restrict__ bf1,
      const float* __restrict__ Wf2, const float* __restrict__ bf2,
      float* __restrict__ out) {
    __shared__ float z[2 * HH];
    __shared__ float t1[50];
    __shared__ float t2[50];
    int gg = blockIdx.x;
    int t = threadIdx.x;

    float c = fmaxf(d_cnt[gg], 1.f);
    for (int d = t; d < 2 * HH; d += 64)
        z[d] = (d < HH) ? d_psum[gg * HH + d] / c : d_pmax[gg * HH + (d - HH)];
    __syncthreads();

    if (t < 50) {
        float s = bf0[t];
        for (int k = 0; k < 2 * HH; k++) s += z[k] * Wf0[k * 50 + t];
        t1[t] = fmaxf(s, 0.f);
    }
    __syncthreads();
    if (t < 50) {
        float s = bf1[t];
        for (int k = 0; k < 50; k++) s += t1[k] * Wf1[k * 50 + t];
        t2[t] = fmaxf(s, 0.f);
    }
    __syncthreads();
    if (t < 10) {
        float s = bf2[t];
        for (int k = 0; k < 50; k++) s += t2[k] * Wf2[k * 10 + t];
        out[gg * 10 + t] = fmaxf(s, 0.f);
    }
}

// ---------------------------------------------------------------------------
static inline int cdiv(long long a, int b) { return (int)((a + b - 1) / b); }

extern "C" void kernel_launch(void* const* d_in, const int* in_sizes, int n_in,
                              void* d_out, int out_size) {
    const float* x      = (const float*)d_in[0];
    const float* xdims  = (const float*)d_in[1];
    const int*   st     = (const int*)d_in[2];
    const int*   ei     = (const int*)d_in[3];
    const int*   batch  = (const int*)d_in[4];
    const float* emb    = (const float*)d_in[5];
    const float* Wl0 = (const float*)d_in[6];
    const float* bl0 = (const float*)d_in[7];
    const float* Wr0 = (const float*)d_in[8];
    const float* g0  = (const float*)d_in[9];
    const float* bn0 = (const float*)d_in[10];
    const float* Wl1 = (const float*)d_in[11];
    const float* bl1 = (const float*)d_in[12];
    const float* Wr1 = (const float*)d_in[13];
    const float* g1  = (const float*)d_in[14];
    const float* bn1 = (const float*)d_in[15];
    const float* Wf0 = (const float*)d_in[16];
    const float* bf0 = (const float*)d_in[17];
    const float* Wf1 = (const float*)d_in[18];
    const float* bf1 = (const float*)d_in[19];
    const float* Wf2 = (const float*)d_in[20];
    const float* bf2 = (const float*)d_in[21];
    float* out = (float*)d_out;

    const int* src = ei;
    const int* dst = ei + EE;

    uint4 *p_h0p, *p_h1p;
    __nv_bfloat16 *p_w0hi, *p_w0lo, *p_w1hi, *p_w1lo;
    cudaGetSymbolAddress((void**)&p_h0p, d_h0p);
    cudaGetSymbolAddress((void**)&p_h1p, d_h1p);
    cudaGetSymbolAddress((void**)&p_w0hi, d_w0hi);
    cudaGetSymbolAddress((void**)&p_w0lo, d_w0lo);
    cudaGetSymbolAddress((void**)&p_w1hi, d_w1hi);
    cudaGetSymbolAddress((void**)&p_w1lo, d_w1lo);

    const int SMEMSZ = 2 * BUFSZ + 67584 + 3072;   // 201728
    cudaFuncSetAttribute((const void*)k_sage_hmma<KP0, false>,
                         cudaFuncAttributeMaxDynamicSharedMemorySize, SMEMSZ);
    cudaFuncSetAttribute((const void*)k_sage_hmma<HH, true>,
                         cudaFuncAttributeMaxDynamicSharedMemorySize, SMEMSZ);

    // init + node features + weight prep + CSR build
    k_initprep<<<cdiv((long long)NN * (KP0 / 4), 256), 256>>>(
        x, xdims, st, emb, Wl0, Wr0, Wl1, Wr1);
    k_deg<<<cdiv(EE, 256), 256>>>(dst);
    k_scan1<<<NSB, SCAN_B>>>();
    k_scan3c<<<cdiv(NN, 256), 256>>>(batch);
    k_fill<<<cdiv(EE, 256), 256>>>(src, dst);

    // ---- layer 0 ----
    k_gatherp0<<<cdiv(NN, 8), 160>>>(p_h0p);
    k_sage_hmma<KP0, false><<<SAGE_GRID, 256, SMEMSZ>>>(
        bl0, g0, bn0, p_h0p, p_w0hi, p_w0lo, p_h1p, nullptr);

    // ---- layer 1 (pooling fused into epilogue) ----
    k_gatherp<<<cdiv(NN, 4), 128>>>(p_h1p);
    k_sage_hmma<HH, true><<<SAGE_GRID, 256, SMEMSZ>>>(
        bl1, g1, bn1, p_h1p, p_w1hi, p_w1lo, nullptr, batch);

    // ---- MLP head ----
    k_mlp<<<GG, 64>>>(Wf0, bf0, Wf1, bf1, Wf2, bf2, out);
}

// round 13
// speedup vs baseline: 1.0044x; 1.0044x over previous
#include <cuda_runtime.h>
#include <cuda_bf16.h>
#include <math.h>
#include <stdint.h>

#define NN 100000
#define EE 600000
#define GG 512
#define HH 128
#define KP0 80          // layer0 K padded (74 -> 80)
#define KR0 74
#define SCAN_B 512
#define NSB ((NN + SCAN_B - 1) / SCAN_B)   // 196
#define CS 132          // smem C row stride (floats)
#define BUFSZ 65536     // per-pipeline-buffer smem stride
#define SAGE_GRID 148

// ---- scratch (device globals; no allocation allowed) ----
// packed layout: per node, per 4-channel group q: uint4{hi01, hi23, lo01, lo23}
__device__ uint4 d_h0p[NN * (KP0 / 4)];
__device__ uint4 d_h1p[NN * (HH / 4)];
__device__ uint4 d_aggp[NN * (HH / 4)];
__device__ __nv_bfloat16 d_w0hi[160 * HH];
__device__ __nv_bfloat16 d_w0lo[160 * HH];
__device__ __nv_bfloat16 d_w1hi[256 * HH];
__device__ __nv_bfloat16 d_w1lo[256 * HH];
__device__ float d_invdeg[NN];
__device__ int   d_degi[NN];
__device__ int   d_cursor[NN];
__device__ int   d_rowstart[NN + 1];
__device__ int   d_eid[EE];
__device__ int   d_bsum[NSB];
__device__ int   d_boff[NSB];
__device__ float d_psum[GG * HH];
__device__ float d_pmax[GG * HH];
__device__ float d_cnt[GG];

// ============================ helpers ======================================
__device__ __forceinline__ uint32_t smem_u32(const void* p) {
    uint32_t a;
    asm("{ .reg .u64 t; cvta.to.shared.u64 t, %1; cvt.u32.u64 %0, t; }"
        : "=r"(a) : "l"(p));
    return a;
}
__device__ __forceinline__ uint32_t sw128(uint32_t off) { return off ^ ((off >> 3) & 0x70); }
__device__ __forceinline__ uint32_t bpack(__nv_bfloat16 a, __nv_bfloat16 b) {
    return ((uint32_t)__bfloat16_as_ushort(b) << 16) | (uint32_t)__bfloat16_as_ushort(a);
}
__device__ __forceinline__ void ldsm4(uint32_t& r0, uint32_t& r1,
                                      uint32_t& r2, uint32_t& r3, uint32_t addr) {
    asm volatile("ldmatrix.sync.aligned.m8n8.x4.shared.b16 {%0,%1,%2,%3}, [%4];"
                 : "=r"(r0), "=r"(r1), "=r"(r2), "=r"(r3) : "r"(addr));
}
__device__ __forceinline__ void mma16816(float* d, const uint32_t* a,
                                         uint32_t b0, uint32_t b1) {
    asm volatile("mma.sync.aligned.m16n8k16.row.col.f32.bf16.bf16.f32 "
                 "{%0,%1,%2,%3}, {%4,%5,%6,%7}, {%8,%9}, {%0,%1,%2,%3};"
                 : "+f"(d[0]), "+f"(d[1]), "+f"(d[2]), "+f"(d[3])
                 : "r"(a[0]), "r"(a[1]), "r"(a[2]), "r"(a[3]), "r"(b0), "r"(b1));
}
__device__ __forceinline__ float2 b2f2(uint32_t u) {
    return __bfloat1622float2(*reinterpret_cast<__nv_bfloat162*>(&u));
}
__device__ __forceinline__ uint4 pack4(float a0, float a1, float a2, float a3) {
    __nv_bfloat16 b0 = __float2bfloat16(a0), b1 = __float2bfloat16(a1);
    __nv_bfloat16 b2 = __float2bfloat16(a2), b3 = __float2bfloat16(a3);
    uint4 r;
    r.x = bpack(b0, b1);
    r.y = bpack(b2, b3);
    r.z = bpack(__float2bfloat16(a0 - __bfloat162float(b0)),
                __float2bfloat16(a1 - __bfloat162float(b1)));
    r.w = bpack(__float2bfloat16(a2 - __bfloat162float(b2)),
                __float2bfloat16(a3 - __bfloat162float(b3)));
    return r;
}
__device__ __forceinline__ void cp_async16(uint32_t dst, const void* src, bool full) {
    int sz = full ? 16 : 0;
    asm volatile("cp.async.cg.shared.global [%0], [%1], 16, %2;"
                 :: "r"(dst), "l"(src), "r"(sz) : "memory");
}
#define CP_COMMIT() asm volatile("cp.async.commit_group;" ::: "memory")
#define CP_WAIT0()  asm volatile("cp.async.wait_group 0;" ::: "memory")

// ===========================================================================
// init (deg/cursor/pool buffers) + packed h0 build + BOTH layers' weight prep
__global__ void k_initprep(const float* __restrict__ x,
                           const float* __restrict__ xd,
                           const int* __restrict__ st,
                           const float* __restrict__ emb,
                           const float* __restrict__ Wl0, const float* __restrict__ Wr0,
                           const float* __restrict__ Wl1, const float* __restrict__ Wr1) {
    int idx = blockIdx.x * blockDim.x + threadIdx.x;
    if (idx < NN) { d_degi[idx] = 0; d_cursor[idx] = 0; }
    if (idx < GG * HH) { d_psum[idx] = 0.f; d_pmax[idx] = __int_as_float(0xFF800000); }
    if (idx < GG) d_cnt[idx] = 0.f;

    constexpr int KT0 = 2 * KP0;          // 160
    constexpr int KT1 = 2 * HH;           // 256
    constexpr int N0 = HH * KT0;          // 20480
    if (idx < N0) {
        int o = idx / KT0;
        int k = idx - o * KT0;
        float w = 0.f;
        const float* W = (k < KP0) ? Wl0 : Wr0;
        int r = (k < KP0) ? k : k - KP0;
        if (r < KR0) w = W[(size_t)r * HH + o];
        __nv_bfloat16 hi = __float2bfloat16(w);
        d_w0hi[idx] = hi;
        d_w0lo[idx] = __float2bfloat16(w - __bfloat162float(hi));
    }
    int idx1 = idx - N0;
    if (idx1 >= 0 && idx1 < HH * KT1) {
        int o = idx1 / KT1;
        int k = idx1 - o * KT1;
        const float* W = (k < HH) ? Wl1 : Wr1;
        int r = (k < HH) ? k : k - HH;
        float w = W[(size_t)r * HH + o];
        __nv_bfloat16 hi = __float2bfloat16(w);
        d_w1hi[idx1] = hi;
        d_w1lo[idx1] = __float2bfloat16(w - __bfloat162float(hi));
    }

    constexpr int C4 = KP0 / 4;
    if (idx >= NN * C4) return;
    int n = idx / C4;
    int q = idx - n * C4;
    float v[4];
#pragma unroll
    for (int t = 0; t < 4; t++) {
        int j = q * 4 + t;
        if (j < 60)      v[t] = x[n * 60 + j];
        else if (j < 62) v[t] = xd[n * 2 + (j - 60)];
        else if (j < 74) v[t] = emb[st[n] * 12 + (j - 62)];
        else             v[t] = 0.f;
    }
    d_h0p[idx] = pack4(v[0], v[1], v[2], v[3]);
}

__global__ void k_deg(const int* __restrict__ dst) {
    int e = blockIdx.x * blockDim.x + threadIdx.x;
    if (e < EE) atomicAdd(&d_degi[dst[e]], 1);
}

__global__ void __launch_bounds__(SCAN_B)
k_scan1() {
    __shared__ int sc[SCAN_B];
    int tid = threadIdx.x;
    int i = blockIdx.x * SCAN_B + tid;
    int v = (i < NN) ? d_degi[i] : 0;
    sc[tid] = v;
    __syncthreads();
#pragma unroll
    for (int off = 1; off < SCAN_B; off <<= 1) {
        int t = (tid >= off) ? sc[tid - off] : 0;
        __syncthreads();
        sc[tid] += t;
        __syncthreads();
    }
    if (i < NN) {
        d_rowstart[i] = sc[tid] - v;
        d_invdeg[i] = 1.f / fmaxf((float)v, 1.f);
    }
    if (tid == SCAN_B - 1) d_bsum[blockIdx.x] = sc[tid];
}

// parallel block-scan over NSB block sums, one 256-thread block
__global__ void __launch_bounds__(256)
k_scan2() {
    __shared__ int sc[256];
    int tid = threadIdx.x;
    int v = (tid < NSB) ? d_bsum[tid] : 0;
    sc[tid] = v;
    __syncthreads();
#pragma unroll
    for (int off = 1; off < 256; off <<= 1) {
        int t = (tid >= off) ? sc[tid - off] : 0;
        __syncthreads();
        sc[tid] += t;
        __syncthreads();
    }
    if (tid < NSB) d_boff[tid] = sc[tid] - v;
    if (tid == 0) d_rowstart[NN] = EE;
}

// rowstart offset + graph count (trivial, no redundant scan)
__global__ void k_scan3c(const int* __restrict__ batch) {
    int i = blockIdx.x * blockDim.x + threadIdx.x;
    if (i < NN) {
        d_rowstart[i] += d_boff[i / SCAN_B];
        atomicAdd(&d_cnt[batch[i]], 1.f);
    }
}

__global__ void k_fill(const int* __restrict__ src, const int* __restrict__ dst) {
    int e = blockIdx.x * blockDim.x + threadIdx.x;
    if (e >= EE) return;
    int dn = dst[e];
    int pos = d_rowstart[dn] + atomicAdd(&d_cursor[dn], 1);
    d_eid[pos] = src[e];
}

// gather aggregation, layer1 (C4 = 32): one warp per node, unroll x2.
__global__ void __launch_bounds__(128)
k_gatherp(const uint4* __restrict__ hp) {
    int n = blockIdx.x * 4 + (threadIdx.x >> 5);
    int lane = threadIdx.x & 31;
    if (n >= NN) return;
    constexpr int C4 = HH / 4;
    int s = d_rowstart[n];
    int e = d_rowstart[n + 1];
    float a0 = 0.f, a1 = 0.f, a2 = 0.f, a3 = 0.f;
    int j = s;
    for (; j + 1 < e; j += 2) {
        int id0 = d_eid[j];
        int id1 = d_eid[j + 1];
        uint4 v0 = hp[(size_t)id0 * C4 + lane];
        uint4 v1 = hp[(size_t)id1 * C4 + lane];
        float2 h01 = b2f2(v0.x), h23 = b2f2(v0.y);
        float2 l01 = b2f2(v0.z), l23 = b2f2(v0.w);
        a0 += h01.x + l01.x; a1 += h01.y + l01.y;
        a2 += h23.x + l23.x; a3 += h23.y + l23.y;
        h01 = b2f2(v1.x); h23 = b2f2(v1.y);
        l01 = b2f2(v1.z); l23 = b2f2(v1.w);
        a0 += h01.x + l01.x; a1 += h01.y + l01.y;
        a2 += h23.x + l23.x; a3 += h23.y + l23.y;
    }
    if (j < e) {
        uint4 v0 = hp[(size_t)d_eid[j] * C4 + lane];
        float2 h01 = b2f2(v0.x), h23 = b2f2(v0.y);
        float2 l01 = b2f2(v0.z), l23 = b2f2(v0.w);
        a0 += h01.x + l01.x; a1 += h01.y + l01.y;
        a2 += h23.x + l23.x; a3 += h23.y + l23.y;
    }
    float inv = d_invdeg[n];
    d_aggp[(size_t)n * C4 + lane] = pack4(a0 * inv, a1 * inv, a2 * inv, a3 * inv);
}

// gather aggregation, layer0 (C4 = 20): 160 threads, 20 lanes/node, 8 nodes/block.
__global__ void __launch_bounds__(160)
k_gatherp0(const uint4* __restrict__ hp) {
    constexpr int C4 = KP0 / 4;           // 20
    int tid = threadIdx.x;
    int n = blockIdx.x * 8 + tid / C4;
    int lane = tid % C4;
    if (n >= NN) return;
    int s = d_rowstart[n];
    int e = d_rowstart[n + 1];
    float a0 = 0.f, a1 = 0.f, a2 = 0.f, a3 = 0.f;
    int j = s;
    for (; j + 1 < e; j += 2) {
        int id0 = d_eid[j];
        int id1 = d_eid[j + 1];
        uint4 v0 = hp[(size_t)id0 * C4 + lane];
        uint4 v1 = hp[(size_t)id1 * C4 + lane];
        float2 h01 = b2f2(v0.x), h23 = b2f2(v0.y);
        float2 l01 = b2f2(v0.z), l23 = b2f2(v0.w);
        a0 += h01.x + l01.x; a1 += h01.y + l01.y;
        a2 += h23.x + l23.x; a3 += h23.y + l23.y;
        h01 = b2f2(v1.x); h23 = b2f2(v1.y);
        l01 = b2f2(v1.z); l23 = b2f2(v1.w);
        a0 += h01.x + l01.x; a1 += h01.y + l01.y;
        a2 += h23.x + l23.x; a3 += h23.y + l23.y;
    }
    if (j < e) {
        uint4 v0 = hp[(size_t)d_eid[j] * C4 + lane];
        float2 h01 = b2f2(v0.x), h23 = b2f2(v0.y);
        float2 l01 = b2f2(v0.z), l23 = b2f2(v0.w);
        a0 += h01.x + l01.x; a1 += h01.y + l01.y;
        a2 += h23.x + l23.x; a3 += h23.y + l23.y;
    }
    float inv = d_invdeg[n];
    d_aggp[(size_t)n * C4 + lane] = pack4(a0 * inv, a1 * inv, a2 * inv, a3 * inv);
}

// ===========================================================================
// Persistent HMMA fused SAGE layer: grid=148, each block streams (tile,chunk)
// pairs with depth-1 software pipelining ACROSS tile boundaries. sC has its
// own smem region so epilogues overlap in-flight staging for the next tile.
// ===========================================================================
template <int KP, bool POOL>
__global__ void __launch_bounds__(256, 1)
k_sage_hmma(const float* __restrict__ bl, const float* __restrict__ g,
            const float* __restrict__ bn,
            const uint4* __restrict__ hp,
            const __nv_bfloat16* __restrict__ whi,
            const __nv_bfloat16* __restrict__ wlo,
            uint4* __restrict__ outp,
            const int* __restrict__ batch) {
    extern __shared__ __align__(128) char smem[];
    constexpr int KT = 2 * KP;
    constexpr int NCH = (KT + 63) / 64;
    constexpr int C4 = KP / 4;
    const uint32_t sb = smem_u32(smem);
    const int tid = threadIdx.x;
    const int wid = tid >> 5;
    const int lid = tid & 31;
    const int wm = wid & 1;
    const int wn = wid >> 1;
    const int G = gridDim.x;

    const int NT = (NN + 127) / 128;
    const int myTiles = ((int)blockIdx.x < NT) ? ((NT - 1 - (int)blockIdx.x) / G + 1) : 0;
    const int total = myTiles * NCH;
    if (total == 0) return;

    float* sC   = (float*)(smem + 2 * BUFSZ);          // 131072, 67584 bytes
    float* s_bl = (float*)(smem + 2 * BUFSZ + 67584);
    float* s_g  = s_bl + 128;
    float* s_bn = s_bl + 256;
    float* s_mu = s_bl + 384;
    float* s_rs = s_bl + 512;
    int*  sbat  = (int*)(s_bl + 640);

    if (tid < 128) { s_bl[tid] = bl[tid]; s_g[tid] = g[tid]; s_bn[tid] = bn[tid]; }

    float acc[4][4][4];
#pragma unroll
    for (int mt = 0; mt < 4; mt++)
#pragma unroll
        for (int nt = 0; nt < 4; nt++)
#pragma unroll
            for (int j = 0; j < 4; j++) acc[mt][nt][j] = 0.f;

    uint4 rh[4], rl[4];

    auto stageA_ldg = [&](int n0s, int c) {
#pragma unroll
        for (int it = 0; it < 4; it++) {
            int idx = tid + it * 256;
            int m = idx >> 3, j = idx & 7;
            int kg = c * 64 + j * 8;
            int n = n0s + m;
            uint4 p0 = make_uint4(0, 0, 0, 0), p1 = make_uint4(0, 0, 0, 0);
            if (n < NN && kg < KT) {
                const uint4* P;
                int kl;
                if (kg < KP) { P = d_aggp; kl = kg; } else { P = hp; kl = kg - KP; }
                size_t base = (size_t)n * C4 + (kl >> 2);
                p0 = P[base]; p1 = P[base + 1];
            }
            rh[it] = make_uint4(p0.x, p0.y, p1.x, p1.y);
            rl[it] = make_uint4(p0.z, p0.w, p1.z, p1.w);
        }
    };
    auto stageA_sts = [&](int pb) {
#pragma unroll
        for (int it = 0; it < 4; it++) {
            int idx = tid + it * 256;
            int m = idx >> 3, j = idx & 7;
            uint32_t sw = sw128((uint32_t)m * 128 + j * 16);
            *(uint4*)(smem + pb * BUFSZ + sw)         = rh[it];
            *(uint4*)(smem + pb * BUFSZ + 16384 + sw) = rl[it];
        }
    };
    auto stageB_cp = [&](int c, int pb) {
#pragma unroll
        for (int it = 0; it < 4; it++) {
            int idx = tid + it * 256;
            int o = idx >> 3, j = idx & 7;
            int kg = c * 64 + j * 8;
            bool ok = (kg < KT);
            size_t off = ok ? ((size_t)o * KT + kg) : 0;
            uint32_t sw = sw128((uint32_t)o * 128 + j * 16);
            cp_async16(sb + pb * BUFSZ + 32768 + sw, &whi[off], ok);
            cp_async16(sb + pb * BUFSZ + 49152 + sw, &wlo[off], ok);
        }
    };

    // ---- prologue: stage stream element 0 ----
    stageA_ldg((int)blockIdx.x * 128, 0);
    stageB_cp(0, 0);
    CP_COMMIT();
    stageA_sts(0);
    CP_WAIT0();
    __syncthreads();

    for (int s = 0; s < total; s++) {
        const int pb = s & 1;
        const int c = s % NCH;
        const int tile = (int)blockIdx.x + (s / NCH) * G;
        const int n0 = tile * 128;

        if (s + 1 < total) {
            int s1 = s + 1;
            int c1 = s1 % NCH;
            int t1 = (int)blockIdx.x + (s1 / NCH) * G;
            stageA_ldg(t1 * 128, c1);
            stageB_cp(c1, pb ^ 1);
            CP_COMMIT();
        }

        // ---- compute chunk c from buffer pb ----
        const uint32_t AHI = sb + pb * BUFSZ, ALO = AHI + 16384;
        const uint32_t BHI = AHI + 32768,     BLO = AHI + 49152;
        const int steps = min(4, (KT - c * 64) / 16);
#pragma unroll
        for (int ks = 0; ks < 4; ks++) {
            if (ks >= steps) break;
            const int kof = ks * 16 + (((lid >> 4) & 1) << 3);
            const int rsub = (lid & 7) + ((lid >> 3) & 1) * 8;

            uint32_t ah[4][4], al[4][4];
#pragma unroll
            for (int mt = 0; mt < 4; mt++) {
                int row = wm * 64 + mt * 16 + rsub;
                uint32_t o = sw128((uint32_t)row * 128 + kof * 2);
                ldsm4(ah[mt][0], ah[mt][1], ah[mt][2], ah[mt][3], AHI + o);
                ldsm4(al[mt][0], al[mt][1], al[mt][2], al[mt][3], ALO + o);
            }
            uint32_t bh[2][4], blo[2][4];
#pragma unroll
            for (int ng = 0; ng < 2; ng++) {
                int rown = wn * 32 + ng * 16 + rsub;
                uint32_t o = sw128((uint32_t)rown * 128 + kof * 2);
                ldsm4(bh[ng][0], bh[ng][1], bh[ng][2], bh[ng][3], BHI + o);
                ldsm4(blo[ng][0], blo[ng][1], blo[ng][2], blo[ng][3], BLO + o);
            }
#pragma unroll
            for (int mt = 0; mt < 4; mt++)
#pragma unroll
                for (int nt = 0; nt < 4; nt++) {
                    int ng = nt >> 1, sel = nt & 1;
                    mma16816(acc[mt][nt], ah[mt], bh[ng][sel], bh[ng][sel + 2]);
                    mma16816(acc[mt][nt], ah[mt], blo[ng][sel], blo[ng][sel + 2]);
                    mma16816(acc[mt][nt], al[mt], bh[ng][sel], bh[ng][sel + 2]);
                }
        }

        if (s + 1 < total) stageA_sts(pb ^ 1);   // free A regs before epilogue

        if (c == NCH - 1) {
            // ================= tile epilogue (overlaps in-flight cp.async) ==
            if (POOL && tid < 128) sbat[tid] = (n0 + tid < NN) ? batch[n0 + tid] : 0;
            __syncthreads();   // prior tile pool reads done; sbat visible
#pragma unroll
            for (int mt = 0; mt < 4; mt++)
#pragma unroll
                for (int nt = 0; nt < 4; nt++) {
                    int r0 = wm * 64 + mt * 16 + (lid >> 2);
                    int c0 = wn * 32 + nt * 8 + 2 * (lid & 3);
                    sC[r0 * CS + c0]           = acc[mt][nt][0];
                    sC[r0 * CS + c0 + 1]       = acc[mt][nt][1];
                    sC[(r0 + 8) * CS + c0]     = acc[mt][nt][2];
                    sC[(r0 + 8) * CS + c0 + 1] = acc[mt][nt][3];
                    acc[mt][nt][0] = 0.f; acc[mt][nt][1] = 0.f;
                    acc[mt][nt][2] = 0.f; acc[mt][nt][3] = 0.f;
                }
            __syncthreads();

            if (tid < 128) {
                float sum = 0.f, sq = 0.f;
                for (int cc = 0; cc < 128; cc++) {
                    float v = sC[tid * CS + cc] + s_bl[cc];
                    sum += v; sq += v * v;
                }
                float mu = sum * (1.f / HH);
                float var = fmaxf(sq * (1.f / HH) - mu * mu, 0.f);
                s_mu[tid] = mu;
                s_rs[tid] = rsqrtf(var + 1e-5f);
            }
            __syncthreads();

            if (POOL) {
                if (tid < 128) {
                    int vrows = min(128, NN - n0);
                    float gc = s_g[tid], bc = s_bn[tid], blc = s_bl[tid];
                    float ps = 0.f, mx = -__int_as_float(0x7F800000);
                    int cur = sbat[0];
                    for (int m = 0; m < vrows; m++) {
                        int b = sbat[m];
                        if (b != cur) {
                            atomicAdd(&d_psum[cur * HH + tid], ps);
                            atomicMax((int*)&d_pmax[cur * HH + tid], __float_as_int(mx));
                            ps = 0.f; mx = -__int_as_float(0x7F800000); cur = b;
                        }
                        float v = sC[m * CS + tid] + blc;
                        float y = fmaxf((v - s_mu[m]) * s_rs[m] * gc + bc, 0.f);
                        ps += y; mx = fmaxf(mx, y);
                    }
                    atomicAdd(&d_psum[cur * HH + tid], ps);
                    atomicMax((int*)&d_pmax[cur * HH + tid], __float_as_int(mx));
                }
            } else {
                for (int idx = tid; idx < 128 * 32; idx += 256) {
                    int m = idx >> 5, q = idx & 31;
                    int n = n0 + m;
                    if (n >= NN) continue;
                    float mu = s_mu[m], rs = s_rs[m];
                    float4 v = *(const float4*)&sC[m * CS + q * 4];
                    float y0 = fmaxf((v.x + s_bl[q*4+0] - mu) * rs * s_g[q*4+0] + s_bn[q*4+0], 0.f);
                    float y1 = fmaxf((v.y + s_bl[q*4+1] - mu) * rs * s_g[q*4+1] + s_bn[q*4+1], 0.f);
                    float y2 = fmaxf((v.z + s_bl[q*4+2] - mu) * rs * s_g[q*4+2] + s_bn[q*4+2], 0.f);
                    float y3 = fmaxf((v.w + s_bl[q*4+3] - mu) * rs * s_g[q*4+3] + s_bn[q*4+3], 0.f);
                    outp[(size_t)n * 32 + q] = pack4(y0, y1, y2, y3);
                }
            }
        }

        if (s + 1 < total) CP_WAIT0();
        __syncthreads();
    }
}

__global__ void __launch_bounds__(64)
k_mlp(const float* __restrict__ Wf0, const float* __restrict__ bf0,
      const float* __restrict__ Wf1, const float* __restrict__ bf1,
      const float* __restrict__ Wf2, const float* __restrict__ bf2,
      float* __restrict__ out) {
    __shared__ float z[2 * HH];
    __shared__ float t1[50];
    __shared__ float t2[50];
    int gg = blockIdx.x;
    int t = threadIdx.x;

    float c = fmaxf(d_cnt[gg], 1.f);
    for (int d = t; d < 2 * HH; d += 64)
        z[d] = (d < HH) ? d_psum[gg * HH + d] / c : d_pmax[gg * HH + (d - HH)];
    __syncthreads();

    if (t < 50) {
        float s = bf0[t];
        for (int k = 0; k < 2 * HH; k++) s += z[k] * Wf0[k * 50 + t];
        t1[t] = fmaxf(s, 0.f);
    }
    __syncthreads();
    if (t < 50) {
        float s = bf1[t];
        for (int k = 0; k < 50; k++) s += t1[k] * Wf1[k * 50 + t];
        t2[t] = fmaxf(s, 0.f);
    }
    __syncthreads();
    if (t < 10) {
        float s = bf2[t];
        for (int k = 0; k < 50; k++) s += t2[k] * Wf2[k * 10 + t];
        out[gg * 10 + t] = fmaxf(s, 0.f);
    }
}

// ---------------------------------------------------------------------------
static inline int cdiv(long long a, int b) { return (int)((a + b - 1) / b); }

extern "C" void kernel_launch(void* const* d_in, const int* in_sizes, int n_in,
                              void* d_out, int out_size) {
    const float* x      = (const float*)d_in[0];
    const float* xdims  = (const float*)d_in[1];
    const int*   st     = (const int*)d_in[2];
    const int*   ei     = (const int*)d_in[3];
    const int*   batch  = (const int*)d_in[4];
    const float* emb    = (const float*)d_in[5];
    const float* Wl0 = (const float*)d_in[6];
    const float* bl0 = (const float*)d_in[7];
    const float* Wr0 = (const float*)d_in[8];
    const float* g0  = (const float*)d_in[9];
    const float* bn0 = (const float*)d_in[10];
    const float* Wl1 = (const float*)d_in[11];
    const float* bl1 = (const float*)d_in[12];
    const float* Wr1 = (const float*)d_in[13];
    const float* g1  = (const float*)d_in[14];
    const float* bn1 = (const float*)d_in[15];
    const float* Wf0 = (const float*)d_in[16];
    const float* bf0 = (const float*)d_in[17];
    const float* Wf1 = (const float*)d_in[18];
    const float* bf1 = (const float*)d_in[19];
    const float* Wf2 = (const float*)d_in[20];
    const float* bf2 = (const float*)d_in[21];
    float* out = (float*)d_out;

    const int* src = ei;
    const int* dst = ei + EE;

    uint4 *p_h0p, *p_h1p;
    __nv_bfloat16 *p_w0hi, *p_w0lo, *p_w1hi, *p_w1lo;
    cudaGetSymbolAddress((void**)&p_h0p, d_h0p);
    cudaGetSymbolAddress((void**)&p_h1p, d_h1p);
    cudaGetSymbolAddress((void**)&p_w0hi, d_w0hi);
    cudaGetSymbolAddress((void**)&p_w0lo, d_w0lo);
    cudaGetSymbolAddress((void**)&p_w1hi, d_w1hi);
    cudaGetSymbolAddress((void**)&p_w1lo, d_w1lo);

    const int SMEMSZ = 2 * BUFSZ + 67584 + 3072;   // 201728
    cudaFuncSetAttribute((const void*)k_sage_hmma<KP0, false>,
                         cudaFuncAttributeMaxDynamicSharedMemorySize, SMEMSZ);
    cudaFuncSetAttribute((const void*)k_sage_hmma<HH, true>,
                         cudaFuncAttributeMaxDynamicSharedMemorySize, SMEMSZ);

    // init + node features + weight prep + CSR build
    k_initprep<<<cdiv((long long)NN * (KP0 / 4), 256), 256>>>(
        x, xdims, st, emb, Wl0, Wr0, Wl1, Wr1);
    k_deg<<<cdiv(EE, 256), 256>>>(dst);
    k_scan1<<<NSB, SCAN_B>>>();
    k_scan2<<<1, 256>>>();
    k_scan3c<<<cdiv(NN, 256), 256>>>(batch);
    k_fill<<<cdiv(EE, 256), 256>>>(src, dst);

    // ---- layer 0 ----
    k_gatherp0<<<cdiv(NN, 8), 160>>>(p_h0p);
    k_sage_hmma<KP0, false><<<SAGE_GRID, 256, SMEMSZ>>>(
        bl0, g0, bn0, p_h0p, p_w0hi, p_w0lo, p_h1p, nullptr);

    // ---- layer 1 (pooling fused into epilogue) ----
    k_gatherp<<<cdiv(NN, 4), 128>>>(p_h1p);
    k_sage_hmma<HH, true><<<SAGE_GRID, 256, SMEMSZ>>>(
        bl1, g1, bn1, p_h1p, p_w1hi, p_w1lo, nullptr, batch);

    // ---- MLP head ----
    k_mlp<<<GG, 64>>>(Wf0, bf0, Wf1, bf1, Wf2, bf2, out);
}

// round 14
// speedup vs baseline: 1.0283x; 1.0238x over previous
#include <cuda_runtime.h>
#include <cuda_bf16.h>
#include <math.h>
#include <stdint.h>

#define NN 100000
#define EE 600000
#define GG 512
#define HH 128
#define KP0 80          // layer0 K padded (74 -> 80)
#define KR0 74
#define SCAN_B 512
#define NSB ((NN + SCAN_B - 1) / SCAN_B)   // 196
#define CS 132          // smem C row stride (floats)
#define BUFSZ 65536     // per-pipeline-buffer smem stride

// ---- scratch (device globals; no allocation allowed) ----
// packed layout: per node, per 4-channel group q: uint4{hi01, hi23, lo01, lo23}
__device__ uint4 d_h0p[NN * (KP0 / 4)];
__device__ uint4 d_h1p[NN * (HH / 4)];
__device__ uint4 d_aggp[NN * (HH / 4)];
__device__ __nv_bfloat16 d_w0hi[160 * HH];
__device__ __nv_bfloat16 d_w0lo[160 * HH];
__device__ __nv_bfloat16 d_w1hi[256 * HH];
__device__ __nv_bfloat16 d_w1lo[256 * HH];
__device__ float d_invdeg[NN];
__device__ int   d_degi[NN];
__device__ int   d_cursor[NN];
__device__ int   d_rowstart[NN + 1];
__device__ int   d_eid[EE];
__device__ int   d_bsum[NSB];
__device__ int   d_boff[NSB];
__device__ int   d_scanctr;
__device__ float d_psum[GG * HH];
__device__ float d_pmax[GG * HH];
__device__ float d_cnt[GG];

// ============================ helpers ======================================
__device__ __forceinline__ uint32_t smem_u32(const void* p) {
    uint32_t a;
    asm("{ .reg .u64 t; cvta.to.shared.u64 t, %1; cvt.u32.u64 %0, t; }"
        : "=r"(a) : "l"(p));
    return a;
}
__device__ __forceinline__ uint32_t sw128(uint32_t off) { return off ^ ((off >> 3) & 0x70); }
__device__ __forceinline__ uint32_t bpack(__nv_bfloat16 a, __nv_bfloat16 b) {
    return ((uint32_t)__bfloat16_as_ushort(b) << 16) | (uint32_t)__bfloat16_as_ushort(a);
}
__device__ __forceinline__ void ldsm4(uint32_t& r0, uint32_t& r1,
                                      uint32_t& r2, uint32_t& r3, uint32_t addr) {
    asm volatile("ldmatrix.sync.aligned.m8n8.x4.shared.b16 {%0,%1,%2,%3}, [%4];"
                 : "=r"(r0), "=r"(r1), "=r"(r2), "=r"(r3) : "r"(addr));
}
__device__ __forceinline__ void mma16816(float* d, const uint32_t* a,
                                         uint32_t b0, uint32_t b1) {
    asm volatile("mma.sync.aligned.m16n8k16.row.col.f32.bf16.bf16.f32 "
                 "{%0,%1,%2,%3}, {%4,%5,%6,%7}, {%8,%9}, {%0,%1,%2,%3};"
                 : "+f"(d[0]), "+f"(d[1]), "+f"(d[2]), "+f"(d[3])
                 : "r"(a[0]), "r"(a[1]), "r"(a[2]), "r"(a[3]), "r"(b0), "r"(b1));
}
__device__ __forceinline__ float2 b2f2(uint32_t u) {
    return __bfloat1622float2(*reinterpret_cast<__nv_bfloat162*>(&u));
}
__device__ __forceinline__ uint4 pack4(float a0, float a1, float a2, float a3) {
    __nv_bfloat16 b0 = __float2bfloat16(a0), b1 = __float2bfloat16(a1);
    __nv_bfloat16 b2 = __float2bfloat16(a2), b3 = __float2bfloat16(a3);
    uint4 r;
    r.x = bpack(b0, b1);
    r.y = bpack(b2, b3);
    r.z = bpack(__float2bfloat16(a0 - __bfloat162float(b0)),
                __float2bfloat16(a1 - __bfloat162float(b1)));
    r.w = bpack(__float2bfloat16(a2 - __bfloat162float(b2)),
                __float2bfloat16(a3 - __bfloat162float(b3)));
    return r;
}
__device__ __forceinline__ void cp_async16(uint32_t dst, const void* src, bool full) {
    int sz = full ? 16 : 0;
    asm volatile("cp.async.cg.shared.global [%0], [%1], 16, %2;"
                 :: "r"(dst), "l"(src), "r"(sz) : "memory");
}
#define CP_COMMIT() asm volatile("cp.async.commit_group;" ::: "memory")
#define CP_WAIT0()  asm volatile("cp.async.wait_group 0;" ::: "memory")

// ===========================================================================
// init (deg/cursor/pool buffers/scan counter) + packed h0 build + weight prep
__global__ void k_initprep(const float* __restrict__ x,
                           const float* __restrict__ xd,
                           const int* __restrict__ st,
                           const float* __restrict__ emb,
                           const float* __restrict__ Wl0, const float* __restrict__ Wr0,
                           const float* __restrict__ Wl1, const float* __restrict__ Wr1) {
    int idx = blockIdx.x * blockDim.x + threadIdx.x;
    if (idx == 0) d_scanctr = 0;
    if (idx < NN) { d_degi[idx] = 0; d_cursor[idx] = 0; }
    if (idx < GG * HH) { d_psum[idx] = 0.f; d_pmax[idx] = __int_as_float(0xFF800000); }
    if (idx < GG) d_cnt[idx] = 0.f;

    constexpr int KT0 = 2 * KP0;          // 160
    constexpr int KT1 = 2 * HH;           // 256
    constexpr int N0 = HH * KT0;          // 20480
    if (idx < N0) {
        int o = idx / KT0;
        int k = idx - o * KT0;
        float w = 0.f;
        const float* W = (k < KP0) ? Wl0 : Wr0;
        int r = (k < KP0) ? k : k - KP0;
        if (r < KR0) w = W[(size_t)r * HH + o];
        __nv_bfloat16 hi = __float2bfloat16(w);
        d_w0hi[idx] = hi;
        d_w0lo[idx] = __float2bfloat16(w - __bfloat162float(hi));
    }
    int idx1 = idx - N0;
    if (idx1 >= 0 && idx1 < HH * KT1) {
        int o = idx1 / KT1;
        int k = idx1 - o * KT1;
        const float* W = (k < HH) ? Wl1 : Wr1;
        int r = (k < HH) ? k : k - HH;
        float w = W[(size_t)r * HH + o];
        __nv_bfloat16 hi = __float2bfloat16(w);
        d_w1hi[idx1] = hi;
        d_w1lo[idx1] = __float2bfloat16(w - __bfloat162float(hi));
    }

    constexpr int C4 = KP0 / 4;
    if (idx >= NN * C4) return;
    int n = idx / C4;
    int q = idx - n * C4;
    float v[4];
#pragma unroll
    for (int t = 0; t < 4; t++) {
        int j = q * 4 + t;
        if (j < 60)      v[t] = x[n * 60 + j];
        else if (j < 62) v[t] = xd[n * 2 + (j - 60)];
        else if (j < 74) v[t] = emb[st[n] * 12 + (j - 62)];
        else             v[t] = 0.f;
    }
    d_h0p[idx] = pack4(v[0], v[1], v[2], v[3]);
}

__global__ void k_deg(const int* __restrict__ dst) {
    int e = blockIdx.x * blockDim.x + threadIdx.x;
    if (e < EE) atomicAdd(&d_degi[dst[e]], 1);
}

// degree scan; the LAST arriving block also scans the block sums (kills scan2)
__global__ void __launch_bounds__(SCAN_B)
k_scan1() {
    __shared__ int sc[SCAN_B];
    __shared__ int lastf;
    int tid = threadIdx.x;
    int i = blockIdx.x * SCAN_B + tid;
    int v = (i < NN) ? d_degi[i] : 0;
    sc[tid] = v;
    __syncthreads();
#pragma unroll
    for (int off = 1; off < SCAN_B; off <<= 1) {
        int t = (tid >= off) ? sc[tid - off] : 0;
        __syncthreads();
        sc[tid] += t;
        __syncthreads();
    }
    if (i < NN) {
        d_rowstart[i] = sc[tid] - v;
        d_invdeg[i] = 1.f / fmaxf((float)v, 1.f);
    }
    if (tid == SCAN_B - 1) d_bsum[blockIdx.x] = sc[tid];
    __syncthreads();

    // decoupled: last block to finish scans the NSB block sums
    if (tid == 0) {
        __threadfence();
        lastf = (atomicAdd(&d_scanctr, 1) == (int)gridDim.x - 1) ? 1 : 0;
    }
    __syncthreads();
    if (lastf) {
        int bv = (tid < NSB) ? d_bsum[tid] : 0;
        sc[tid] = bv;
        __syncthreads();
#pragma unroll
        for (int off = 1; off < SCAN_B; off <<= 1) {
            int t = (tid >= off) ? sc[tid - off] : 0;
            __syncthreads();
            sc[tid] += t;
            __syncthreads();
        }
        if (tid < NSB) d_boff[tid] = sc[tid] - bv;
        if (tid == 0) d_rowstart[NN] = EE;
    }
}

// rowstart offset + graph count
__global__ void k_scan3c(const int* __restrict__ batch) {
    int i = blockIdx.x * blockDim.x + threadIdx.x;
    if (i < NN) {
        d_rowstart[i] += d_boff[i / SCAN_B];
        atomicAdd(&d_cnt[batch[i]], 1.f);
    }
}

__global__ void k_fill(const int* __restrict__ src, const int* __restrict__ dst) {
    int e = blockIdx.x * blockDim.x + threadIdx.x;
    if (e >= EE) return;
    int dn = dst[e];
    int pos = d_rowstart[dn] + atomicAdd(&d_cursor[dn], 1);
    d_eid[pos] = src[e];
}

// gather aggregation, layer1 (C4 = 32): one warp per node, unroll x2.
__global__ void __launch_bounds__(128)
k_gatherp(const uint4* __restrict__ hp) {
    int n = blockIdx.x * 4 + (threadIdx.x >> 5);
    int lane = threadIdx.x & 31;
    if (n >= NN) return;
    constexpr int C4 = HH / 4;
    int s = d_rowstart[n];
    int e = d_rowstart[n + 1];
    float a0 = 0.f, a1 = 0.f, a2 = 0.f, a3 = 0.f;
    int j = s;
    for (; j + 1 < e; j += 2) {
        int id0 = d_eid[j];
        int id1 = d_eid[j + 1];
        uint4 v0 = hp[(size_t)id0 * C4 + lane];
        uint4 v1 = hp[(size_t)id1 * C4 + lane];
        float2 h01 = b2f2(v0.x), h23 = b2f2(v0.y);
        float2 l01 = b2f2(v0.z), l23 = b2f2(v0.w);
        a0 += h01.x + l01.x; a1 += h01.y + l01.y;
        a2 += h23.x + l23.x; a3 += h23.y + l23.y;
        h01 = b2f2(v1.x); h23 = b2f2(v1.y);
        l01 = b2f2(v1.z); l23 = b2f2(v1.w);
        a0 += h01.x + l01.x; a1 += h01.y + l01.y;
        a2 += h23.x + l23.x; a3 += h23.y + l23.y;
    }
    if (j < e) {
        uint4 v0 = hp[(size_t)d_eid[j] * C4 + lane];
        float2 h01 = b2f2(v0.x), h23 = b2f2(v0.y);
        float2 l01 = b2f2(v0.z), l23 = b2f2(v0.w);
        a0 += h01.x + l01.x; a1 += h01.y + l01.y;
        a2 += h23.x + l23.x; a3 += h23.y + l23.y;
    }
    float inv = d_invdeg[n];
    d_aggp[(size_t)n * C4 + lane] = pack4(a0 * inv, a1 * inv, a2 * inv, a3 * inv);
}

// gather aggregation, layer0 (C4 = 20): 160 threads, 20 lanes/node, 8 nodes/block.
__global__ void __launch_bounds__(160)
k_gatherp0(const uint4* __restrict__ hp) {
    constexpr int C4 = KP0 / 4;           // 20
    int tid = threadIdx.x;
    int n = blockIdx.x * 8 + tid / C4;
    int lane = tid % C4;
    if (n >= NN) return;
    int s = d_rowstart[n];
    int e = d_rowstart[n + 1];
    float a0 = 0.f, a1 = 0.f, a2 = 0.f, a3 = 0.f;
    int j = s;
    for (; j + 1 < e; j += 2) {
        int id0 = d_eid[j];
        int id1 = d_eid[j + 1];
        uint4 v0 = hp[(size_t)id0 * C4 + lane];
        uint4 v1 = hp[(size_t)id1 * C4 + lane];
        float2 h01 = b2f2(v0.x), h23 = b2f2(v0.y);
        float2 l01 = b2f2(v0.z), l23 = b2f2(v0.w);
        a0 += h01.x + l01.x; a1 += h01.y + l01.y;
        a2 += h23.x + l23.x; a3 += h23.y + l23.y;
        h01 = b2f2(v1.x); h23 = b2f2(v1.y);
        l01 = b2f2(v1.z); l23 = b2f2(v1.w);
        a0 += h01.x + l01.x; a1 += h01.y + l01.y;
        a2 += h23.x + l23.x; a3 += h23.y + l23.y;
    }
    if (j < e) {
        uint4 v0 = hp[(size_t)d_eid[j] * C4 + lane];
        float2 h01 = b2f2(v0.x), h23 = b2f2(v0.y);
        float2 l01 = b2f2(v0.z), l23 = b2f2(v0.w);
        a0 += h01.x + l01.x; a1 += h01.y + l01.y;
        a2 += h23.x + l23.x; a3 += h23.y + l23.y;
    }
    float inv = d_invdeg[n];
    d_aggp[(size_t)n * C4 + lane] = pack4(a0 * inv, a1 * inv, a2 * inv, a3 * inv);
}

// ===========================================================================
// HMMA fused SAGE layer (R11 config): per-tile blocks, double-buffered smem;
// A via early LDG->regs->STS, B via cp.async. Tile 128x128, K chunks of 64.
// ===========================================================================
template <int KP, bool POOL>
__global__ void __launch_bounds__(256, 1)
k_sage_hmma(const float* __restrict__ bl, const float* __restrict__ g,
            const float* __restrict__ bn,
            const uint4* __restrict__ hp,
            const __nv_bfloat16* __restrict__ whi,
            const __nv_bfloat16* __restrict__ wlo,
            uint4* __restrict__ outp,
            const int* __restrict__ batch) {
    extern __shared__ __align__(128) char smem[];
    constexpr int KT = 2 * KP;
    constexpr int NCH = (KT + 63) / 64;
    constexpr int C4 = KP / 4;
    const uint32_t sb = smem_u32(smem);
    const int tid = threadIdx.x;
    const int wid = tid >> 5;
    const int lid = tid & 31;
    const int n0 = blockIdx.x * 128;
    const int wm = wid & 1;
    const int wn = wid >> 1;

    float* sC   = (float*)smem;                    // aliases buf0/1, used post-loop
    float* s_bl = (float*)(smem + 2 * BUFSZ);      // 131072
    float* s_g  = s_bl + 128;
    float* s_bn = s_bl + 256;
    float* s_mu = s_bl + 384;
    float* s_rs = s_bl + 512;
    int*  sbat  = (int*)(s_bl + 640);

    if (tid < 128) {
        s_bl[tid] = bl[tid]; s_g[tid] = g[tid]; s_bn[tid] = bn[tid];
        if (POOL) sbat[tid] = (n0 + tid < NN) ? batch[n0 + tid] : 0;
    }

    float acc[4][4][4];
#pragma unroll
    for (int mt = 0; mt < 4; mt++)
#pragma unroll
        for (int nt = 0; nt < 4; nt++)
#pragma unroll
            for (int j = 0; j < 4; j++) acc[mt][nt][j] = 0.f;

    uint4 rh[4], rl[4];

    auto stageA_ldg = [&](int c) {
#pragma unroll
        for (int it = 0; it < 4; it++) {
            int idx = tid + it * 256;
            int m = idx >> 3, j = idx & 7;
            int kg = c * 64 + j * 8;
            int n = n0 + m;
            uint4 p0 = make_uint4(0, 0, 0, 0), p1 = make_uint4(0, 0, 0, 0);
            if (n < NN && kg < KT) {
                const uint4* P;
                int kl;
                if (kg < KP) { P = d_aggp; kl = kg; } else { P = hp; kl = kg - KP; }
                size_t base = (size_t)n * C4 + (kl >> 2);
                p0 = P[base]; p1 = P[base + 1];
            }
            rh[it] = make_uint4(p0.x, p0.y, p1.x, p1.y);
            rl[it] = make_uint4(p0.z, p0.w, p1.z, p1.w);
        }
    };
    auto stageA_sts = [&](int pb) {
#pragma unroll
        for (int it = 0; it < 4; it++) {
            int idx = tid + it * 256;
            int m = idx >> 3, j = idx & 7;
            uint32_t sw = sw128((uint32_t)m * 128 + j * 16);
            *(uint4*)(smem + pb * BUFSZ + sw)         = rh[it];
            *(uint4*)(smem + pb * BUFSZ + 16384 + sw) = rl[it];
        }
    };
    auto stageB_cp = [&](int c, int pb) {
#pragma unroll
        for (int it = 0; it < 4; it++) {
            int idx = tid + it * 256;
            int o = idx >> 3, j = idx & 7;
            int kg = c * 64 + j * 8;
            bool ok = (kg < KT);
            size_t off = ok ? ((size_t)o * KT + kg) : 0;
            uint32_t sw = sw128((uint32_t)o * 128 + j * 16);
            cp_async16(sb + pb * BUFSZ + 32768 + sw, &whi[off], ok);
            cp_async16(sb + pb * BUFSZ + 49152 + sw, &wlo[off], ok);
        }
    };

    // ---- prologue: fill buffer 0 with chunk 0 ----
    stageA_ldg(0);
    stageB_cp(0, 0);
    CP_COMMIT();
    stageA_sts(0);
    CP_WAIT0();
    __syncthreads();

    for (int c = 0; c < NCH; c++) {
        const int pb = c & 1;
        if (c + 1 < NCH) {
            stageA_ldg(c + 1);          // LDGs in flight during compute
            stageB_cp(c + 1, pb ^ 1);
            CP_COMMIT();
        }
        // ---- compute from buffer pb ----
        const uint32_t AHI = sb + pb * BUFSZ,      ALO = AHI + 16384;
        const uint32_t BHI = AHI + 32768,          BLO = AHI + 49152;
        const int steps = min(4, (KT - c * 64) / 16);
#pragma unroll
        for (int ks = 0; ks < 4; ks++) {
            if (ks >= steps) break;
            const int kof = ks * 16 + (((lid >> 4) & 1) << 3);
            const int rsub = (lid & 7) + ((lid >> 3) & 1) * 8;

            uint32_t ah[4][4], al[4][4];
#pragma unroll
            for (int mt = 0; mt < 4; mt++) {
                int row = wm * 64 + mt * 16 + rsub;
                uint32_t o = sw128((uint32_t)row * 128 + kof * 2);
                ldsm4(ah[mt][0], ah[mt][1], ah[mt][2], ah[mt][3], AHI + o);
                ldsm4(al[mt][0], al[mt][1], al[mt][2], al[mt][3], ALO + o);
            }
            uint32_t bh[2][4], blo[2][4];
#pragma unroll
            for (int ng = 0; ng < 2; ng++) {
                int rown = wn * 32 + ng * 16 + rsub;
                uint32_t o = sw128((uint32_t)rown * 128 + kof * 2);
                ldsm4(bh[ng][0], bh[ng][1], bh[ng][2], bh[ng][3], BHI + o);
                ldsm4(blo[ng][0], blo[ng][1], blo[ng][2], blo[ng][3], BLO + o);
            }
#pragma unroll
            for (int mt = 0; mt < 4; mt++)
#pragma unroll
                for (int nt = 0; nt < 4; nt++) {
                    int ng = nt >> 1, sel = nt & 1;
                    mma16816(acc[mt][nt], ah[mt], bh[ng][sel], bh[ng][sel + 2]);
                    mma16816(acc[mt][nt], ah[mt], blo[ng][sel], blo[ng][sel + 2]);
                    mma16816(acc[mt][nt], al[mt], bh[ng][sel], bh[ng][sel + 2]);
                }
        }
        if (c + 1 < NCH) {
            stageA_sts(pb ^ 1);         // LDG results land after compute
            CP_WAIT0();
        }
        __syncthreads();
    }

    // ---- store C frags to smem ----
#pragma unroll
    for (int mt = 0; mt < 4; mt++)
#pragma unroll
        for (int nt = 0; nt < 4; nt++) {
            int r0 = wm * 64 + mt * 16 + (lid >> 2);
            int c0 = wn * 32 + nt * 8 + 2 * (lid & 3);
            sC[r0 * CS + c0]           = acc[mt][nt][0];
            sC[r0 * CS + c0 + 1]       = acc[mt][nt][1];
            sC[(r0 + 8) * CS + c0]     = acc[mt][nt][2];
            sC[(r0 + 8) * CS + c0 + 1] = acc[mt][nt][3];
        }
    __syncthreads();

    // ---- LN stats per node row ----
    if (tid < 128) {
        float sum = 0.f, sq = 0.f;
        for (int cc = 0; cc < 128; cc++) {
            float v = sC[tid * CS + cc] + s_bl[cc];
            sum += v; sq += v * v;
        }
        float mu = sum * (1.f / HH);
        float var = fmaxf(sq * (1.f / HH) - mu * mu, 0.f);
        s_mu[tid] = mu;
        s_rs[tid] = rsqrtf(var + 1e-5f);
    }
    __syncthreads();

    if (POOL) {
        if (tid < 128) {
            int vrows = min(128, NN - n0);
            float gc = s_g[tid], bc = s_bn[tid], blc = s_bl[tid];
            float s = 0.f, mx = -__int_as_float(0x7F800000);
            int cur = sbat[0];
            for (int m = 0; m < vrows; m++) {
                int b = sbat[m];
                if (b != cur) {
                    atomicAdd(&d_psum[cur * HH + tid], s);
                    atomicMax((int*)&d_pmax[cur * HH + tid], __float_as_int(mx));
                    s = 0.f; mx = -__int_as_float(0x7F800000); cur = b;
                }
                float v = sC[m * CS + tid] + blc;
                float y = fmaxf((v - s_mu[m]) * s_rs[m] * gc + bc, 0.f);
                s += y; mx = fmaxf(mx, y);
            }
            atomicAdd(&d_psum[cur * HH + tid], s);
            atomicMax((int*)&d_pmax[cur * HH + tid], __float_as_int(mx));
        }
    } else {
        for (int idx = tid; idx < 128 * 32; idx += 256) {
            int m = idx >> 5, q = idx & 31;
            int n = n0 + m;
            if (n >= NN) continue;
            float mu = s_mu[m], rs = s_rs[m];
            float4 v = *(const float4*)&sC[m * CS + q * 4];
            float y0 = fmaxf((v.x + s_bl[q*4+0] - mu) * rs * s_g[q*4+0] + s_bn[q*4+0], 0.f);
            float y1 = fmaxf((v.y + s_bl[q*4+1] - mu) * rs * s_g[q*4+1] + s_bn[q*4+1], 0.f);
            float y2 = fmaxf((v.z + s_bl[q*4+2] - mu) * rs * s_g[q*4+2] + s_bn[q*4+2], 0.f);
            float y3 = fmaxf((v.w + s_bl[q*4+3] - mu) * rs * s_g[q*4+3] + s_bn[q*4+3], 0.f);
            outp[(size_t)n * 32 + q] = pack4(y0, y1, y2, y3);
        }
    }
}

__global__ void __launch_bounds__(64)
k_mlp(const float* __restrict__ Wf0, const float* __restrict__ bf0,
      const float* __restrict__ Wf1, const float* __restrict__ bf1,
      const float* __restrict__ Wf2, const float* __restrict__ bf2,
      float* __restrict__ out) {
    __shared__ float z[2 * HH];
    __shared__ float t1[50];
    __shared__ float t2[50];
    int gg = blockIdx.x;
    int t = threadIdx.x;

    float c = fmaxf(d_cnt[gg], 1.f);
    for (int d = t; d < 2 * HH; d += 64)
        z[d] = (d < HH) ? d_psum[gg * HH + d] / c : d_pmax[gg * HH + (d - HH)];
    __syncthreads();

    if (t < 50) {
        float s = bf0[t];
        for (int k = 0; k < 2 * HH; k++) s += z[k] * Wf0[k * 50 + t];
        t1[t] = fmaxf(s, 0.f);
    }
    __syncthreads();
    if (t < 50) {
        float s = bf1[t];
        for (int k = 0; k < 50; k++) s += t1[k] * Wf1[k * 50 + t];
        t2[t] = fmaxf(s, 0.f);
    }
    __syncthreads();
    if (t < 10) {
        float s = bf2[t];
        for (int k = 0; k < 50; k++) s += t2[k] * Wf2[k * 10 + t];
        out[gg * 10 + t] = fmaxf(s, 0.f);
    }
}

// ---------------------------------------------------------------------------
static inline int cdiv(long long a, int b) { return (int)((a + b - 1) / b); }

extern "C" void kernel_launch(void* const* d_in, const int* in_sizes, int n_in,
                              void* d_out, int out_size) {
    const float* x      = (const float*)d_in[0];
    const float* xdims  = (const float*)d_in[1];
    const int*   st     = (const int*)d_in[2];
    const int*   ei     = (const int*)d_in[3];
    const int*   batch  = (const int*)d_in[4];
    const float* emb    = (const float*)d_in[5];
    const float* Wl0 = (const float*)d_in[6];
    const float* bl0 = (const float*)d_in[7];
    const float* Wr0 = (const float*)d_in[8];
    const float* g0  = (const float*)d_in[9];
    const float* bn0 = (const float*)d_in[10];
    const float* Wl1 = (const float*)d_in[11];
    const float* bl1 = (const float*)d_in[12];
    const float* Wr1 = (const float*)d_in[13];
    const float* g1  = (const float*)d_in[14];
    const float* bn1 = (const float*)d_in[15];
    const float* Wf0 = (const float*)d_in[16];
    const float* bf0 = (const float*)d_in[17];
    const float* Wf1 = (const float*)d_in[18];
    const float* bf1 = (const float*)d_in[19];
    const float* Wf2 = (const float*)d_in[20];
    const float* bf2 = (const float*)d_in[21];
    float* out = (float*)d_out;

    const int* src = ei;
    const int* dst = ei + EE;

    uint4 *p_h0p, *p_h1p;
    __nv_bfloat16 *p_w0hi, *p_w0lo, *p_w1hi, *p_w1lo;
    cudaGetSymbolAddress((void**)&p_h0p, d_h0p);
    cudaGetSymbolAddress((void**)&p_h1p, d_h1p);
    cudaGetSymbolAddress((void**)&p_w0hi, d_w0hi);
    cudaGetSymbolAddress((void**)&p_w0lo, d_w0lo);
    cudaGetSymbolAddress((void**)&p_w1hi, d_w1hi);
    cudaGetSymbolAddress((void**)&p_w1lo, d_w1lo);

    const int SMEMSZ = 2 * BUFSZ + 3072;   // 134144
    cudaFuncSetAttribute((const void*)k_sage_hmma<KP0, false>,
                         cudaFuncAttributeMaxDynamicSharedMemorySize, SMEMSZ);
    cudaFuncSetAttribute((const void*)k_sage_hmma<HH, true>,
                         cudaFuncAttributeMaxDynamicSharedMemorySize, SMEMSZ);

    // init + node features + weight prep + CSR build (scan2 folded into scan1)
    k_initprep<<<cdiv((long long)NN * (KP0 / 4), 256), 256>>>(
        x, xdims, st, emb, Wl0, Wr0, Wl1, Wr1);
    k_deg<<<cdiv(EE, 256), 256>>>(dst);
    k_scan1<<<NSB, SCAN_B>>>();
    k_scan3c<<<cdiv(NN, 256), 256>>>(batch);
    k_fill<<<cdiv(EE, 256), 256>>>(src, dst);

    // ---- layer 0 ----
    k_gatherp0<<<cdiv(NN, 8), 160>>>(p_h0p);
    k_sage_hmma<KP0, false><<<cdiv(NN, 128), 256, SMEMSZ>>>(
        bl0, g0, bn0, p_h0p, p_w0hi, p_w0lo, p_h1p, nullptr);

    // ---- layer 1 (pooling fused into epilogue) ----
    k_gatherp<<<cdiv(NN, 4), 128>>>(p_h1p);
    k_sage_hmma<HH, true><<<cdiv(NN, 128), 256, SMEMSZ>>>(
        bl1, g1, bn1, p_h1p, p_w1hi, p_w1lo, nullptr, batch);

    // ---- MLP head ----
    k_mlp<<<GG, 64>>>(Wf0, bf0, Wf1, bf1, Wf2, bf2, out);
}

// round 15
// speedup vs baseline: 1.0894x; 1.0595x over previous
#include <cuda_runtime.h>
#include <cuda_bf16.h>
#include <math.h>
#include <stdint.h>

#define NN 100000
#define EE 600000
#define GG 512
#define HH 128
#define KP0 80          // layer0 K padded (74 -> 80)
#define KR0 74
#define SCAN_B 512
#define NSB ((NN + SCAN_B - 1) / SCAN_B)   // 196
#define CS 132          // smem C row stride (floats)
#define BUFSZ 65536     // per-pipeline-buffer smem stride

// ---- scratch (device globals; no allocation allowed) ----
// packed layout: per node, per 4-channel group q: uint4{hi01, hi23, lo01, lo23}
__device__ uint4 d_h0p[NN * (KP0 / 4)];
__device__ uint4 d_h1p[NN * (HH / 4)];
__device__ uint4 d_aggp[NN * (HH / 4)];
__device__ __nv_bfloat16 d_w0hi[160 * HH];
__device__ __nv_bfloat16 d_w0lo[160 * HH];
__device__ __nv_bfloat16 d_w1hi[256 * HH];
__device__ __nv_bfloat16 d_w1lo[256 * HH];
__device__ float d_invdeg[NN];
__device__ int   d_degi[NN];
__device__ int   d_cursor[NN];
__device__ int   d_rowstart[NN + 1];
__device__ int   d_eid[EE];
__device__ int   d_bsum[NSB];
__device__ int   d_boff[NSB];
__device__ int   d_scanctr;
__device__ float d_psum[GG * HH];
__device__ float d_pmax[GG * HH];
__device__ float d_cnt[GG];

// ============================ helpers ======================================
__device__ __forceinline__ uint32_t smem_u32(const void* p) {
    uint32_t a;
    asm("{ .reg .u64 t; cvta.to.shared.u64 t, %1; cvt.u32.u64 %0, t; }"
        : "=r"(a) : "l"(p));
    return a;
}
__device__ __forceinline__ uint32_t sw128(uint32_t off) { return off ^ ((off >> 3) & 0x70); }
__device__ __forceinline__ uint32_t bpack(__nv_bfloat16 a, __nv_bfloat16 b) {
    return ((uint32_t)__bfloat16_as_ushort(b) << 16) | (uint32_t)__bfloat16_as_ushort(a);
}
__device__ __forceinline__ void ldsm4(uint32_t& r0, uint32_t& r1,
                                      uint32_t& r2, uint32_t& r3, uint32_t addr) {
    asm volatile("ldmatrix.sync.aligned.m8n8.x4.shared.b16 {%0,%1,%2,%3}, [%4];"
                 : "=r"(r0), "=r"(r1), "=r"(r2), "=r"(r3) : "r"(addr));
}
__device__ __forceinline__ void mma16816(float* d, const uint32_t* a,
                                         uint32_t b0, uint32_t b1) {
    asm volatile("mma.sync.aligned.m16n8k16.row.col.f32.bf16.bf16.f32 "
                 "{%0,%1,%2,%3}, {%4,%5,%6,%7}, {%8,%9}, {%0,%1,%2,%3};"
                 : "+f"(d[0]), "+f"(d[1]), "+f"(d[2]), "+f"(d[3])
                 : "r"(a[0]), "r"(a[1]), "r"(a[2]), "r"(a[3]), "r"(b0), "r"(b1));
}
__device__ __forceinline__ float2 b2f2(uint32_t u) {
    return __bfloat1622float2(*reinterpret_cast<__nv_bfloat162*>(&u));
}
__device__ __forceinline__ uint4 pack4(float a0, float a1, float a2, float a3) {
    __nv_bfloat16 b0 = __float2bfloat16(a0), b1 = __float2bfloat16(a1);
    __nv_bfloat16 b2 = __float2bfloat16(a2), b3 = __float2bfloat16(a3);
    uint4 r;
    r.x = bpack(b0, b1);
    r.y = bpack(b2, b3);
    r.z = bpack(__float2bfloat16(a0 - __bfloat162float(b0)),
                __float2bfloat16(a1 - __bfloat162float(b1)));
    r.w = bpack(__float2bfloat16(a2 - __bfloat162float(b2)),
                __float2bfloat16(a3 - __bfloat162float(b3)));
    return r;
}
__device__ __forceinline__ void cp_async16(uint32_t dst, const void* src, bool full) {
    int sz = full ? 16 : 0;
    asm volatile("cp.async.cg.shared.global [%0], [%1], 16, %2;"
                 :: "r"(dst), "l"(src), "r"(sz) : "memory");
}
#define CP_COMMIT() asm volatile("cp.async.commit_group;" ::: "memory")
#define CP_WAIT0()  asm volatile("cp.async.wait_group 0;" ::: "memory")

// ===========================================================================
// init (deg/cursor/pool buffers/scan counter) + packed h0 build + weight prep
__global__ void k_initprep(const float* __restrict__ x,
                           const float* __restrict__ xd,
                           const int* __restrict__ st,
                           const float* __restrict__ emb,
                           const float* __restrict__ Wl0, const float* __restrict__ Wr0,
                           const float* __restrict__ Wl1, const float* __restrict__ Wr1) {
    int idx = blockIdx.x * blockDim.x + threadIdx.x;
    if (idx == 0) d_scanctr = 0;
    if (idx < NN) { d_degi[idx] = 0; d_cursor[idx] = 0; }
    if (idx < GG * HH) { d_psum[idx] = 0.f; d_pmax[idx] = __int_as_float(0xFF800000); }
    if (idx < GG) d_cnt[idx] = 0.f;

    constexpr int KT0 = 2 * KP0;          // 160
    constexpr int KT1 = 2 * HH;           // 256
    constexpr int N0 = HH * KT0;          // 20480
    if (idx < N0) {
        int o = idx / KT0;
        int k = idx - o * KT0;
        float w = 0.f;
        const float* W = (k < KP0) ? Wl0 : Wr0;
        int r = (k < KP0) ? k : k - KP0;
        if (r < KR0) w = W[(size_t)r * HH + o];
        __nv_bfloat16 hi = __float2bfloat16(w);
        d_w0hi[idx] = hi;
        d_w0lo[idx] = __float2bfloat16(w - __bfloat162float(hi));
    }
    int idx1 = idx - N0;
    if (idx1 >= 0 && idx1 < HH * KT1) {
        int o = idx1 / KT1;
        int k = idx1 - o * KT1;
        const float* W = (k < HH) ? Wl1 : Wr1;
        int r = (k < HH) ? k : k - HH;
        float w = W[(size_t)r * HH + o];
        __nv_bfloat16 hi = __float2bfloat16(w);
        d_w1hi[idx1] = hi;
        d_w1lo[idx1] = __float2bfloat16(w - __bfloat162float(hi));
    }

    constexpr int C4 = KP0 / 4;
    if (idx >= NN * C4) return;
    int n = idx / C4;
    int q = idx - n * C4;
    float v[4];
#pragma unroll
    for (int t = 0; t < 4; t++) {
        int j = q * 4 + t;
        if (j < 60)      v[t] = x[n * 60 + j];
        else if (j < 62) v[t] = xd[n * 2 + (j - 60)];
        else if (j < 74) v[t] = emb[st[n] * 12 + (j - 62)];
        else             v[t] = 0.f;
    }
    d_h0p[idx] = pack4(v[0], v[1], v[2], v[3]);
}

__global__ void k_deg(const int* __restrict__ dst) {
    int e = blockIdx.x * blockDim.x + threadIdx.x;
    if (e < EE) atomicAdd(&d_degi[dst[e]], 1);
}

// degree scan; the LAST arriving block also scans the block sums
__global__ void __launch_bounds__(SCAN_B)
k_scan1() {
    __shared__ int sc[SCAN_B];
    __shared__ int lastf;
    int tid = threadIdx.x;
    int i = blockIdx.x * SCAN_B + tid;
    int v = (i < NN) ? d_degi[i] : 0;
    sc[tid] = v;
    __syncthreads();
#pragma unroll
    for (int off = 1; off < SCAN_B; off <<= 1) {
        int t = (tid >= off) ? sc[tid - off] : 0;
        __syncthreads();
        sc[tid] += t;
        __syncthreads();
    }
    if (i < NN) {
        d_rowstart[i] = sc[tid] - v;
        d_invdeg[i] = 1.f / fmaxf((float)v, 1.f);
    }
    if (tid == SCAN_B - 1) d_bsum[blockIdx.x] = sc[tid];
    __syncthreads();

    // decoupled: last block to finish scans the NSB block sums
    if (tid == 0) {
        __threadfence();
        lastf = (atomicAdd(&d_scanctr, 1) == (int)gridDim.x - 1) ? 1 : 0;
    }
    __syncthreads();
    if (lastf) {
        int bv = (tid < NSB) ? d_bsum[tid] : 0;
        sc[tid] = bv;
        __syncthreads();
#pragma unroll
        for (int off = 1; off < SCAN_B; off <<= 1) {
            int t = (tid >= off) ? sc[tid - off] : 0;
            __syncthreads();
            sc[tid] += t;
            __syncthreads();
        }
        if (tid < NSB) d_boff[tid] = sc[tid] - bv;
        if (tid == 0) d_rowstart[NN] = EE;
    }
}

// rowstart offset + graph count (warp-aggregated atomics; batch sorted)
__global__ void k_scan3c(const int* __restrict__ batch) {
    int i = blockIdx.x * blockDim.x + threadIdx.x;
    if (i < NN) {
        d_rowstart[i] += d_boff[i / SCAN_B];
        int b = batch[i];
        unsigned act = __activemask();
        unsigned mask = __match_any_sync(act, b);
        int leader = __ffs(mask) - 1;
        if ((threadIdx.x & 31) == leader)
            atomicAdd(&d_cnt[b], (float)__popc(mask));
    }
}

__global__ void k_fill(const int* __restrict__ src, const int* __restrict__ dst) {
    int e = blockIdx.x * blockDim.x + threadIdx.x;
    if (e >= EE) return;
    int dn = dst[e];
    int pos = d_rowstart[dn] + atomicAdd(&d_cursor[dn], 1);
    d_eid[pos] = src[e];
}

// gather aggregation, layer1 (C4 = 32): one warp per node, unroll x2.
__global__ void __launch_bounds__(128)
k_gatherp(const uint4* __restrict__ hp) {
    int n = blockIdx.x * 4 + (threadIdx.x >> 5);
    int lane = threadIdx.x & 31;
    if (n >= NN) return;
    constexpr int C4 = HH / 4;
    int s = d_rowstart[n];
    int e = d_rowstart[n + 1];
    float a0 = 0.f, a1 = 0.f, a2 = 0.f, a3 = 0.f;
    int j = s;
    for (; j + 1 < e; j += 2) {
        int id0 = d_eid[j];
        int id1 = d_eid[j + 1];
        uint4 v0 = hp[(size_t)id0 * C4 + lane];
        uint4 v1 = hp[(size_t)id1 * C4 + lane];
        float2 h01 = b2f2(v0.x), h23 = b2f2(v0.y);
        float2 l01 = b2f2(v0.z), l23 = b2f2(v0.w);
        a0 += h01.x + l01.x; a1 += h01.y + l01.y;
        a2 += h23.x + l23.x; a3 += h23.y + l23.y;
        h01 = b2f2(v1.x); h23 = b2f2(v1.y);
        l01 = b2f2(v1.z); l23 = b2f2(v1.w);
        a0 += h01.x + l01.x; a1 += h01.y + l01.y;
        a2 += h23.x + l23.x; a3 += h23.y + l23.y;
    }
    if (j < e) {
        uint4 v0 = hp[(size_t)d_eid[j] * C4 + lane];
        float2 h01 = b2f2(v0.x), h23 = b2f2(v0.y);
        float2 l01 = b2f2(v0.z), l23 = b2f2(v0.w);
        a0 += h01.x + l01.x; a1 += h01.y + l01.y;
        a2 += h23.x + l23.x; a3 += h23.y + l23.y;
    }
    float inv = d_invdeg[n];
    d_aggp[(size_t)n * C4 + lane] = pack4(a0 * inv, a1 * inv, a2 * inv, a3 * inv);
}

// gather aggregation, layer0 (C4 = 20): 160 threads, 20 lanes/node, 8 nodes/block.
__global__ void __launch_bounds__(160)
k_gatherp0(const uint4* __restrict__ hp) {
    constexpr int C4 = KP0 / 4;           // 20
    int tid = threadIdx.x;
    int n = blockIdx.x * 8 + tid / C4;
    int lane = tid % C4;
    if (n >= NN) return;
    int s = d_rowstart[n];
    int e = d_rowstart[n + 1];
    float a0 = 0.f, a1 = 0.f, a2 = 0.f, a3 = 0.f;
    int j = s;
    for (; j + 1 < e; j += 2) {
        int id0 = d_eid[j];
        int id1 = d_eid[j + 1];
        uint4 v0 = hp[(size_t)id0 * C4 + lane];
        uint4 v1 = hp[(size_t)id1 * C4 + lane];
        float2 h01 = b2f2(v0.x), h23 = b2f2(v0.y);
        float2 l01 = b2f2(v0.z), l23 = b2f2(v0.w);
        a0 += h01.x + l01.x; a1 += h01.y + l01.y;
        a2 += h23.x + l23.x; a3 += h23.y + l23.y;
        h01 = b2f2(v1.x); h23 = b2f2(v1.y);
        l01 = b2f2(v1.z); l23 = b2f2(v1.w);
        a0 += h01.x + l01.x; a1 += h01.y + l01.y;
        a2 += h23.x + l23.x; a3 += h23.y + l23.y;
    }
    if (j < e) {
        uint4 v0 = hp[(size_t)d_eid[j] * C4 + lane];
        float2 h01 = b2f2(v0.x), h23 = b2f2(v0.y);
        float2 l01 = b2f2(v0.z), l23 = b2f2(v0.w);
        a0 += h01.x + l01.x; a1 += h01.y + l01.y;
        a2 += h23.x + l23.x; a3 += h23.y + l23.y;
    }
    float inv = d_invdeg[n];
    d_aggp[(size_t)n * C4 + lane] = pack4(a0 * inv, a1 * inv, a2 * inv, a3 * inv);
}

// ===========================================================================
// HMMA fused SAGE layer (R11 config): per-tile blocks, double-buffered smem;
// A via early LDG->regs->STS, B via cp.async. Tile 128x128, K chunks of 64.
// ===========================================================================
template <int KP, bool POOL>
__global__ void __launch_bounds__(256, 1)
k_sage_hmma(const float* __restrict__ bl, const float* __restrict__ g,
            const float* __restrict__ bn,
            const uint4* __restrict__ hp,
            const __nv_bfloat16* __restrict__ whi,
            const __nv_bfloat16* __restrict__ wlo,
            uint4* __restrict__ outp,
            const int* __restrict__ batch) {
    extern __shared__ __align__(128) char smem[];
    constexpr int KT = 2 * KP;
    constexpr int NCH = (KT + 63) / 64;
    constexpr int C4 = KP / 4;
    const uint32_t sb = smem_u32(smem);
    const int tid = threadIdx.x;
    const int wid = tid >> 5;
    const int lid = tid & 31;
    const int n0 = blockIdx.x * 128;
    const int wm = wid & 1;
    const int wn = wid >> 1;

    float* sC   = (float*)smem;                    // aliases buf0/1, used post-loop
    float* s_bl = (float*)(smem + 2 * BUFSZ);      // 131072
    float* s_g  = s_bl + 128;
    float* s_bn = s_bl + 256;
    float* s_mu = s_bl + 384;
    float* s_rs = s_bl + 512;
    int*  sbat  = (int*)(s_bl + 640);

    if (tid < 128) {
        s_bl[tid] = bl[tid]; s_g[tid] = g[tid]; s_bn[tid] = bn[tid];
        if (POOL) sbat[tid] = (n0 + tid < NN) ? batch[n0 + tid] : 0;
    }

    float acc[4][4][4];
#pragma unroll
    for (int mt = 0; mt < 4; mt++)
#pragma unroll
        for (int nt = 0; nt < 4; nt++)
#pragma unroll
            for (int j = 0; j < 4; j++) acc[mt][nt][j] = 0.f;

    uint4 rh[4], rl[4];

    auto stageA_ldg = [&](int c) {
#pragma unroll
        for (int it = 0; it < 4; it++) {
            int idx = tid + it * 256;
            int m = idx >> 3, j = idx & 7;
            int kg = c * 64 + j * 8;
            int n = n0 + m;
            uint4 p0 = make_uint4(0, 0, 0, 0), p1 = make_uint4(0, 0, 0, 0);
            if (n < NN && kg < KT) {
                const uint4* P;
                int kl;
                if (kg < KP) { P = d_aggp; kl = kg; } else { P = hp; kl = kg - KP; }
                size_t base = (size_t)n * C4 + (kl >> 2);
                p0 = P[base]; p1 = P[base + 1];
            }
            rh[it] = make_uint4(p0.x, p0.y, p1.x, p1.y);
            rl[it] = make_uint4(p0.z, p0.w, p1.z, p1.w);
        }
    };
    auto stageA_sts = [&](int pb) {
#pragma unroll
        for (int it = 0; it < 4; it++) {
            int idx = tid + it * 256;
            int m = idx >> 3, j = idx & 7;
            uint32_t sw = sw128((uint32_t)m * 128 + j * 16);
            *(uint4*)(smem + pb * BUFSZ + sw)         = rh[it];
            *(uint4*)(smem + pb * BUFSZ + 16384 + sw) = rl[it];
        }
    };
    auto stageB_cp = [&](int c, int pb) {
#pragma unroll
        for (int it = 0; it < 4; it++) {
            int idx = tid + it * 256;
            int o = idx >> 3, j = idx & 7;
            int kg = c * 64 + j * 8;
            bool ok = (kg < KT);
            size_t off = ok ? ((size_t)o * KT + kg) : 0;
            uint32_t sw = sw128((uint32_t)o * 128 + j * 16);
            cp_async16(sb + pb * BUFSZ + 32768 + sw, &whi[off], ok);
            cp_async16(sb + pb * BUFSZ + 49152 + sw, &wlo[off], ok);
        }
    };

    // ---- prologue: fill buffer 0 with chunk 0 ----
    stageA_ldg(0);
    stageB_cp(0, 0);
    CP_COMMIT();
    stageA_sts(0);
    CP_WAIT0();
    __syncthreads();

    for (int c = 0; c < NCH; c++) {
        const int pb = c & 1;
        if (c + 1 < NCH) {
            stageA_ldg(c + 1);          // LDGs in flight during compute
            stageB_cp(c + 1, pb ^ 1);
            CP_COMMIT();
        }
        // ---- compute from buffer pb ----
        const uint32_t AHI = sb + pb * BUFSZ,      ALO = AHI + 16384;
        const uint32_t BHI = AHI + 32768,          BLO = AHI + 49152;
        const int steps = min(4, (KT - c * 64) / 16);
#pragma unroll
        for (int ks = 0; ks < 4; ks++) {
            if (ks >= steps) break;
            const int kof = ks * 16 + (((lid >> 4) & 1) << 3);
            const int rsub = (lid & 7) + ((lid >> 3) & 1) * 8;

            uint32_t ah[4][4], al[4][4];
#pragma unroll
            for (int mt = 0; mt < 4; mt++) {
                int row = wm * 64 + mt * 16 + rsub;
                uint32_t o = sw128((uint32_t)row * 128 + kof * 2);
                ldsm4(ah[mt][0], ah[mt][1], ah[mt][2], ah[mt][3], AHI + o);
                ldsm4(al[mt][0], al[mt][1], al[mt][2], al[mt][3], ALO + o);
            }
            uint32_t bh[2][4], blo[2][4];
#pragma unroll
            for (int ng = 0; ng < 2; ng++) {
                int rown = wn * 32 + ng * 16 + rsub;
                uint32_t o = sw128((uint32_t)rown * 128 + kof * 2);
                ldsm4(bh[ng][0], bh[ng][1], bh[ng][2], bh[ng][3], BHI + o);
                ldsm4(blo[ng][0], blo[ng][1], blo[ng][2], blo[ng][3], BLO + o);
            }
#pragma unroll
            for (int mt = 0; mt < 4; mt++)
#pragma unroll
                for (int nt = 0; nt < 4; nt++) {
                    int ng = nt >> 1, sel = nt & 1;
                    mma16816(acc[mt][nt], ah[mt], bh[ng][sel], bh[ng][sel + 2]);
                    mma16816(acc[mt][nt], ah[mt], blo[ng][sel], blo[ng][sel + 2]);
                    mma16816(acc[mt][nt], al[mt], bh[ng][sel], bh[ng][sel + 2]);
                }
        }
        if (c + 1 < NCH) {
            stageA_sts(pb ^ 1);         // LDG results land after compute
            CP_WAIT0();
        }
        __syncthreads();
    }

    // ---- store C frags to smem ----
#pragma unroll
    for (int mt = 0; mt < 4; mt++)
#pragma unroll
        for (int nt = 0; nt < 4; nt++) {
            int r0 = wm * 64 + mt * 16 + (lid >> 2);
            int c0 = wn * 32 + nt * 8 + 2 * (lid & 3);
            sC[r0 * CS + c0]           = acc[mt][nt][0];
            sC[r0 * CS + c0 + 1]       = acc[mt][nt][1];
            sC[(r0 + 8) * CS + c0]     = acc[mt][nt][2];
            sC[(r0 + 8) * CS + c0 + 1] = acc[mt][nt][3];
        }
    __syncthreads();

    // ---- LN stats per node row ----
    if (tid < 128) {
        float sum = 0.f, sq = 0.f;
        for (int cc = 0; cc < 128; cc++) {
            float v = sC[tid * CS + cc] + s_bl[cc];
            sum += v; sq += v * v;
        }
        float mu = sum * (1.f / HH);
        float var = fmaxf(sq * (1.f / HH) - mu * mu, 0.f);
        s_mu[tid] = mu;
        s_rs[tid] = rsqrtf(var + 1e-5f);
    }
    __syncthreads();

    if (POOL) {
        if (tid < 128) {
            int vrows = min(128, NN - n0);
            float gc = s_g[tid], bc = s_bn[tid], blc = s_bl[tid];
            float s = 0.f, mx = -__int_as_float(0x7F800000);
            int cur = sbat[0];
            for (int m = 0; m < vrows; m++) {
                int b = sbat[m];
                if (b != cur) {
                    atomicAdd(&d_psum[cur * HH + tid], s);
                    atomicMax((int*)&d_pmax[cur * HH + tid], __float_as_int(mx));
                    s = 0.f; mx = -__int_as_float(0x7F800000); cur = b;
                }
                float v = sC[m * CS + tid] + blc;
                float y = fmaxf((v - s_mu[m]) * s_rs[m] * gc + bc, 0.f);
                s += y; mx = fmaxf(mx, y);
            }
            atomicAdd(&d_psum[cur * HH + tid], s);
            atomicMax((int*)&d_pmax[cur * HH + tid], __float_as_int(mx));
        }
    } else {
        for (int idx = tid; idx < 128 * 32; idx += 256) {
            int m = idx >> 5, q = idx & 31;
            int n = n0 + m;
            if (n >= NN) continue;
            float mu = s_mu[m], rs = s_rs[m];
            float4 v = *(const float4*)&sC[m * CS + q * 4];
            float y0 = fmaxf((v.x + s_bl[q*4+0] - mu) * rs * s_g[q*4+0] + s_bn[q*4+0], 0.f);
            float y1 = fmaxf((v.y + s_bl[q*4+1] - mu) * rs * s_g[q*4+1] + s_bn[q*4+1], 0.f);
            float y2 = fmaxf((v.z + s_bl[q*4+2] - mu) * rs * s_g[q*4+2] + s_bn[q*4+2], 0.f);
            float y3 = fmaxf((v.w + s_bl[q*4+3] - mu) * rs * s_g[q*4+3] + s_bn[q*4+3], 0.f);
            outp[(size_t)n * 32 + q] = pack4(y0, y1, y2, y3);
        }
    }
}

__global__ void __launch_bounds__(64)
k_mlp(const float* __restrict__ Wf0, const float* __restrict__ bf0,
      const float* __restrict__ Wf1, const float* __restrict__ bf1,
      const float* __restrict__ Wf2, const float* __restrict__ bf2,
      float* __restrict__ out) {
    __shared__ float z[2 * HH];
    __shared__ float t1[50];
    __shared__ float t2[50];
    int gg = blockIdx.x;
    int t = threadIdx.x;

    float c = fmaxf(d_cnt[gg], 1.f);
    for (int d = t; d < 2 * HH; d += 64)
        z[d] = (d < HH) ? d_psum[gg * HH + d] / c : d_pmax[gg * HH + (d - HH)];
    __syncthreads();

    if (t < 50) {
        float s = bf0[t];
        for (int k = 0; k < 2 * HH; k++) s += z[k] * Wf0[k * 50 + t];
        t1[t] = fmaxf(s, 0.f);
    }
    __syncthreads();
    if (t < 50) {
        float s = bf1[t];
        for (int k = 0; k < 50; k++) s += t1[k] * Wf1[k * 50 + t];
        t2[t] = fmaxf(s, 0.f);
    }
    __syncthreads();
    if (t < 10) {
        float s = bf2[t];
        for (int k = 0; k < 50; k++) s += t2[k] * Wf2[k * 10 + t];
        out[gg * 10 + t] = fmaxf(s, 0.f);
    }
}

// ---------------------------------------------------------------------------
static inline int cdiv(long long a, int b) { return (int)((a + b - 1) / b); }

extern "C" void kernel_launch(void* const* d_in, const int* in_sizes, int n_in,
                              void* d_out, int out_size) {
    const float* x      = (const float*)d_in[0];
    const float* xdims  = (const float*)d_in[1];
    const int*   st     = (const int*)d_in[2];
    const int*   ei     = (const int*)d_in[3];
    const int*   batch  = (const int*)d_in[4];
    const float* emb    = (const float*)d_in[5];
    const float* Wl0 = (const float*)d_in[6];
    const float* bl0 = (const float*)d_in[7];
    const float* Wr0 = (const float*)d_in[8];
    const float* g0  = (const float*)d_in[9];
    const float* bn0 = (const float*)d_in[10];
    const float* Wl1 = (const float*)d_in[11];
    const float* bl1 = (const float*)d_in[12];
    const float* Wr1 = (const float*)d_in[13];
    const float* g1  = (const float*)d_in[14];
    const float* bn1 = (const float*)d_in[15];
    const float* Wf0 = (const float*)d_in[16];
    const float* bf0 = (const float*)d_in[17];
    const float* Wf1 = (const float*)d_in[18];
    const float* bf1 = (const float*)d_in[19];
    const float* Wf2 = (const float*)d_in[20];
    const float* bf2 = (const float*)d_in[21];
    float* out = (float*)d_out;

    const int* src = ei;
    const int* dst = ei + EE;

    uint4 *p_h0p, *p_h1p;
    __nv_bfloat16 *p_w0hi, *p_w0lo, *p_w1hi, *p_w1lo;
    cudaGetSymbolAddress((void**)&p_h0p, d_h0p);
    cudaGetSymbolAddress((void**)&p_h1p, d_h1p);
    cudaGetSymbolAddress((void**)&p_w0hi, d_w0hi);
    cudaGetSymbolAddress((void**)&p_w0lo, d_w0lo);
    cudaGetSymbolAddress((void**)&p_w1hi, d_w1hi);
    cudaGetSymbolAddress((void**)&p_w1lo, d_w1lo);

    const int SMEMSZ = 2 * BUFSZ + 3072;   // 134144
    cudaFuncSetAttribute((const void*)k_sage_hmma<KP0, false>,
                         cudaFuncAttributeMaxDynamicSharedMemorySize, SMEMSZ);
    cudaFuncSetAttribute((const void*)k_sage_hmma<HH, true>,
                         cudaFuncAttributeMaxDynamicSharedMemorySize, SMEMSZ);

    // init + node features + weight prep + CSR build
    k_initprep<<<cdiv((long long)NN * (KP0 / 4), 256), 256>>>(
        x, xdims, st, emb, Wl0, Wr0, Wl1, Wr1);
    k_deg<<<cdiv(EE, 256), 256>>>(dst);
    k_scan1<<<NSB, SCAN_B>>>();
    k_scan3c<<<cdiv(NN, 256), 256>>>(batch);
    k_fill<<<cdiv(EE, 256), 256>>>(src, dst);

    // ---- layer 0 ----
    k_gatherp0<<<cdiv(NN, 8), 160>>>(p_h0p);
    k_sage_hmma<KP0, false><<<cdiv(NN, 128), 256, SMEMSZ>>>(
        bl0, g0, bn0, p_h0p, p_w0hi, p_w0lo, p_h1p, nullptr);

    // ---- layer 1 (pooling fused into epilogue) ----
    k_gatherp<<<cdiv(NN, 4), 128>>>(p_h1p);
    k_sage_hmma<HH, true><<<cdiv(NN, 128), 256, SMEMSZ>>>(
        bl1, g1, bn1, p_h1p, p_w1hi, p_w1lo, nullptr, batch);

    // ---- MLP head ----
    k_mlp<<<GG, 64>>>(Wf0, bf0, Wf1, bf1, Wf2, bf2, out);
}